// round 6
// baseline (speedup 1.0000x reference)
#include <cuda_runtime.h>
#include <cuda_bf16.h>
#include <cfloat>

// ---------------------------------------------------------------------------
// VectorQuantizer (VQ-VAE) fused pipeline, sm_100a
// (Round-6 resubmit: R5 source never ran -- broker container failed twice.
//  Identical kernel so the R5 prediction gets measured.)
//
// Argmin on tensor cores, exactness decoupled from TC numerics:
//   Pass A: bf16 mma.sync(m16n8k16) approximate distances + per-row running
//           min + margin-collection of candidates (margin 5e-4 >> 2x bf16 err).
//   Pass B: exact reference-rounded rescreen of ~10 candidates/row,
//           winner via atomicMin on (v_bits<<32)|code packed key
//           (exact value order + lowest-index tie-break).
// ---------------------------------------------------------------------------

#define NROWS 32768
#define KN    4096
#define DIM   64

// pass A tiling
#define AM    128            // rows per CTA
#define ABLK  (NROWS / AM)   // 256 CTAs
#define ACH   128            // codes per chunk
#define NACH  (KN / ACH)     // 32
#define LDT   72             // smem tile row stride (halves): conflict-free ldmatrix
#define MARGIN 5e-4f
#define CAND_CAP (1u << 22)  // 4M candidate slots

// output offsets (elements)
#define O_ZQ   0
#define O_IND  2097152
#define O_LOSS 2129920
#define O_NE   2129921
#define O_NCS  2392065
#define O_NW   2396161

// scratch
__device__ float              g_zz[NROWS];
__device__ float              g_e2[KN];
__device__ float              g_counts[KN];
__device__ float              g_dw[KN * DIM];
__device__ float              g_cs[KN];
__device__ float              g_losssum;
__device__ unsigned long long g_best[NROWS];      // (v_bits<<32)|code
__device__ unsigned           g_cand[CAND_CAP];   // (row<<12)|code
__device__ unsigned           g_ncand;
__device__ __nv_bfloat16      g_zb[NROWS * DIM];
__device__ __nv_bfloat16      g_eb[KN * DIM];

__device__ __forceinline__ unsigned smem_u32(const void* p) {
    unsigned r;
    asm("{ .reg .u64 t; cvta.to.shared.u64 t, %1; cvt.u32.u64 %0, t; }"
        : "=r"(r) : "l"(p));
    return r;
}

#define MMA16816(c, A, B0, B1) \
    asm volatile("mma.sync.aligned.m16n8k16.row.col.f32.bf16.bf16.f32 " \
        "{%0,%1,%2,%3}, {%4,%5,%6,%7}, {%8,%9}, {%0,%1,%2,%3};" \
        : "+f"((c)[0]), "+f"((c)[1]), "+f"((c)[2]), "+f"((c)[3]) \
        : "r"((A)[0]), "r"((A)[1]), "r"((A)[2]), "r"((A)[3]), \
          "r"(B0), "r"(B1))

#define CP_ASYNC8(dst, src) \
    asm volatile("cp.async.ca.shared.global [%0], [%1], 8;" \
        :: "r"(dst), "l"(src))

// ---------------------------------------------------------------------------
// K0: zero scratch, init g_best/g_ncand, ||e||^2, ||z||^2 (exact reference
// rounding: sequential fadd_rn(fmul_rn)), bf16 copies of z and emb.
// ---------------------------------------------------------------------------
__global__ void k_prep(const float* __restrict__ z, const float* __restrict__ emb) {
    int i = blockIdx.x * blockDim.x + threadIdx.x;   // 65536 threads
    int stride = gridDim.x * blockDim.x;
    for (int j = i; j < KN * DIM; j += stride) {
        g_dw[j] = 0.f;
        g_eb[j] = __float2bfloat16(emb[j]);
    }
    for (int j = i; j < NROWS * DIM; j += stride)
        g_zb[j] = __float2bfloat16(z[j]);
    if (i < KN) {
        g_counts[i] = 0.f;
        const float* e = emb + (size_t)i * DIM;
        float s = 0.f;
        #pragma unroll
        for (int d = 0; d < DIM; d++) {
            float v = __ldg(e + d);
            s = __fadd_rn(s, __fmul_rn(v, v));
        }
        g_e2[i] = s;
    }
    if (i < NROWS) {
        g_best[i] = 0xFFFFFFFFFFFFFFFFull;
        const float* zr = z + (size_t)i * DIM;
        float s = 0.f;
        #pragma unroll
        for (int d = 0; d < DIM; d++) {
            float v = __ldg(zr + d);
            s = __fadd_rn(s, __fmul_rn(v, v));
        }
        g_zz[i] = s;
    }
    if (i == 0) { g_losssum = 0.f; g_ncand = 0u; }
}

// ---------------------------------------------------------------------------
// K1 (pass A): bf16 tensor-core distance scan + candidate collection.
// 256 threads = 8 warps; warp_m = w>>1 (32 rows), warp_n = w&1 (64 codes).
// smem: zt[128][72]h, et[2][128][72]h (cp.async double buffer),
//       e2s[2][128]f (staged as e2+1 so s' > 0), rowmin[128]u (float bits).
// ---------------------------------------------------------------------------
__global__ void __launch_bounds__(256, 2) k_passA() {
    extern __shared__ __align__(16) char smA[];
    __nv_bfloat16* zt = (__nv_bfloat16*)smA;                  // 9216 halves
    float*    e2s    = (float*)(smA + 55296);                 // 2*128 floats
    unsigned* rowmin = (unsigned*)(smA + 56320);              // 128

    const int tid  = threadIdx.x;
    const int lane = tid & 31;
    const int w    = tid >> 5;
    const int wm   = w >> 1;        // 0..3
    const int wn   = w & 1;         // 0..1
    const int gid  = lane >> 2;     // fragment row group
    const int qid  = lane & 3;      // fragment col pair
    const int r0   = blockIdx.x * AM;

    // ---- stage z tile (plain, once) ----
    const uint2* zb2 = (const uint2*)g_zb;
    #pragma unroll
    for (int it = 0; it < 8; it++) {
        int i  = tid + it * 256;       // 2048
        int r  = i >> 4;
        int c4 = i & 15;
        *(uint2*)(zt + r * LDT + c4 * 4) = zb2[(size_t)(r0 + r) * 16 + c4];
    }
    if (tid < AM) rowmin[tid] = __float_as_uint(3.0f);

    // ---- prefetch e chunk 0 ----
    {
        unsigned etb = smem_u32(zt + 9216);
        const char* src0 = (const char*)g_eb;
        #pragma unroll
        for (int it = 0; it < 8; it++) {
            int i  = tid + it * 256;
            int r  = i >> 4;
            int c4 = i & 15;
            CP_ASYNC8(etb + (unsigned)(r * LDT + c4 * 4) * 2,
                      src0 + ((size_t)r * 64 + c4 * 4) * 2);
        }
        asm volatile("cp.async.commit_group;");
        if (tid < ACH) e2s[tid] = __ldg(&g_e2[tid]) + 1.0f;
    }
    __syncthreads();   // zt visible

    // ---- A fragments (held across all chunks) ----
    unsigned a[2][4][4];
    {
        unsigned ztb = smem_u32(zt);
        #pragma unroll
        for (int tm = 0; tm < 2; tm++)
            #pragma unroll
            for (int kt = 0; kt < 4; kt++) {
                int R0 = wm * 32 + tm * 16;
                unsigned addr = ztb +
                    (unsigned)((R0 + (lane & 15)) * LDT + kt * 16 +
                               ((lane >> 4) << 3)) * 2;
                asm volatile(
                    "ldmatrix.sync.aligned.m8n8.x4.shared.b16 {%0,%1,%2,%3}, [%4];"
                    : "=r"(a[tm][kt][0]), "=r"(a[tm][kt][1]),
                      "=r"(a[tm][kt][2]), "=r"(a[tm][kt][3])
                    : "r"(addr));
            }
    }

    for (int ch = 0; ch < NACH; ch++) {
        asm volatile("cp.async.wait_group 0;");
        __syncthreads();   // current et/e2s visible; prev compute done

        if (ch + 1 < NACH) {
            int nb2 = (ch + 1) & 1;
            unsigned etb = smem_u32(zt + 9216 + nb2 * 9216);
            const char* src = (const char*)g_eb +
                              (size_t)(ch + 1) * ACH * 64 * 2;
            #pragma unroll
            for (int it = 0; it < 8; it++) {
                int i  = tid + it * 256;
                int r  = i >> 4;
                int c4 = i & 15;
                CP_ASYNC8(etb + (unsigned)(r * LDT + c4 * 4) * 2,
                          src + ((size_t)r * 64 + c4 * 4) * 2);
            }
            asm volatile("cp.async.commit_group;");
            if (tid < ACH)
                e2s[nb2 * ACH + tid] = __ldg(&g_e2[(ch + 1) * ACH + tid]) + 1.0f;
        }

        const int cb = ch & 1;
        unsigned et_base = smem_u32(zt + 9216 + cb * 9216);
        const float* e2c = e2s + cb * ACH;

        #pragma unroll
        for (int nt = 0; nt < 8; nt++) {
            const int nb = wn * 64 + nt * 8;

            unsigned b0[4], b1[4];
            #pragma unroll
            for (int kt = 0; kt < 4; kt++) {
                unsigned addr = et_base +
                    (unsigned)((nb + (lane & 7)) * LDT + kt * 16 +
                               (((lane >> 3) & 1) << 3)) * 2;
                asm volatile(
                    "ldmatrix.sync.aligned.m8n8.x2.shared.b16 {%0,%1}, [%2];"
                    : "=r"(b0[kt]), "=r"(b1[kt]) : "r"(addr));
            }

            float c0[4] = {0.f, 0.f, 0.f, 0.f};
            float c1[4] = {0.f, 0.f, 0.f, 0.f};
            #pragma unroll
            for (int kt = 0; kt < 4; kt++) {
                MMA16816(c0, a[0][kt], b0[kt], b1[kt]);
                MMA16816(c1, a[1][kt], b0[kt], b1[kt]);
            }

            const float e2p0 = e2c[nb + qid * 2];
            const float e2p1 = e2c[nb + qid * 2 + 1];

            #pragma unroll
            for (int tm = 0; tm < 2; tm++) {
                const float* cc = tm ? c1 : c0;
                #pragma unroll
                for (int j = 0; j < 4; j++) {
                    float s = fmaf(-2.f, cc[j], (j & 1) ? e2p1 : e2p0);
                    int rl = wm * 32 + tm * 16 + gid + (j >> 1) * 8;
                    float cur = __uint_as_float(rowmin[rl]);
                    bool take = (s <= cur + MARGIN);
                    if (s < cur) atomicMin(&rowmin[rl], __float_as_uint(s));
                    unsigned mk = __ballot_sync(0xffffffffu, take);
                    if (mk) {
                        int leader = __ffs(mk) - 1;
                        unsigned base = 0;
                        if (lane == leader)
                            base = atomicAdd(&g_ncand, (unsigned)__popc(mk));
                        base = __shfl_sync(0xffffffffu, base, leader);
                        if (take) {
                            unsigned pos = base +
                                __popc(mk & ((1u << lane) - 1u));
                            unsigned code = (unsigned)(ch * ACH + nb +
                                                       qid * 2 + (j & 1));
                            if (pos < CAND_CAP)
                                g_cand[pos] = ((unsigned)(r0 + rl) << 12) | code;
                        }
                    }
                }
            }
        }
    }
}

// ---------------------------------------------------------------------------
// K2 (pass B): exact reference-rounded rescreen of collected candidates.
// v = fsub_rn(fadd_rn(zz, ee), 2*dot), dot = sequential fp32 FMA chain
// (R3/R4-proven). Winner per row: atomicMin on (v_bits<<32)|code -> exact
// value order + lowest-index tie-break. v ~ 64 > 0, so uint order == float.
// ---------------------------------------------------------------------------
__global__ void k_rescreen(const float* __restrict__ z,
                           const float* __restrict__ emb) {
    unsigned n = g_ncand;
    if (n > CAND_CAP) n = CAND_CAP;
    for (unsigned i = blockIdx.x * blockDim.x + threadIdx.x; i < n;
         i += gridDim.x * blockDim.x) {
        unsigned cd = g_cand[i];
        int row  = (int)(cd >> 12);
        int code = (int)(cd & 4095u);
        const float* zr = z   + (size_t)row  * DIM;
        const float* er = emb + (size_t)code * DIM;
        float acc = 0.f;
        #pragma unroll
        for (int d = 0; d < DIM; d++)
            acc = __fmaf_rn(zr[d], __ldg(er + d), acc);
        float v = __fsub_rn(__fadd_rn(g_zz[row], g_e2[code]),
                            __fmul_rn(2.f, acc));
        unsigned long long key =
            ((unsigned long long)__float_as_uint(v) << 32) | (unsigned)code;
        atomicMin(&g_best[row], key);
    }
}

// ---------------------------------------------------------------------------
// K3: gather z_q, straight-through output, loss partial, scatter counts/dw,
// write indices output.
// ---------------------------------------------------------------------------
__global__ void k_scatter(const float* __restrict__ z, const float* __restrict__ emb,
                          float* __restrict__ out)
{
    int row = blockIdx.x * 8 + (threadIdx.x >> 5);
    int ln  = threadIdx.x & 31;
    int idx = (int)(unsigned)(g_best[row] & 0xffffffffull);
    const float* zr = z   + (size_t)row * DIM;
    const float* er = emb + (size_t)idx * DIM;
    float* zq = out + O_ZQ + (size_t)row * DIM;
    float l = 0.f;
    #pragma unroll
    for (int t = 0; t < 2; t++) {
        int j = ln + 32 * t;
        float zv = zr[j], ev = __ldg(er + j);
        zq[j] = __fadd_rn(zv, __fsub_rn(ev, zv));
        float dd = __fsub_rn(zv, ev);
        l += dd * dd;
        atomicAdd(&g_dw[idx * DIM + j], zv);
    }
    if (ln == 0) {
        atomicAdd(&g_counts[idx], 1.f);
        out[O_IND + row] = (float)idx;
    }
    #pragma unroll
    for (int o = 16; o; o >>= 1) l += __shfl_xor_sync(0xffffffffu, l, o);
    __shared__ float sl[8];
    if (ln == 0) sl[threadIdx.x >> 5] = l;
    __syncthreads();
    if (threadIdx.x == 0) {
        float s = 0.f;
        #pragma unroll
        for (int w = 0; w < 8; w++) s += sl[w];
        atomicAdd(&g_losssum, s);
    }
}

// ---------------------------------------------------------------------------
// K4: new_cluster_size, n, normalized cluster size, loss (single block)
// ---------------------------------------------------------------------------
__global__ void k_fin1(const float* __restrict__ ema_cs, float* __restrict__ out)
{
    int tid = threadIdx.x;  // 1024
    float ncs[4];
    float s = 0.f;
    #pragma unroll
    for (int j = 0; j < 4; j++) {
        int k = tid + j * 1024;
        float v = 0.99f * ema_cs[k] + 0.01f * g_counts[k];
        ncs[j] = v; s += v;
        out[O_NCS + k] = v;
    }
    __shared__ float sp[32];
    #pragma unroll
    for (int o = 16; o; o >>= 1) s += __shfl_xor_sync(0xffffffffu, s, o);
    if ((tid & 31) == 0) sp[tid >> 5] = s;
    __syncthreads();
    if (tid < 32) {
        float v = sp[tid];
        #pragma unroll
        for (int o = 16; o; o >>= 1) v += __shfl_xor_sync(0xffffffffu, v, o);
        if (tid == 0) sp[0] = v;
    }
    __syncthreads();
    float n = sp[0];
    float denom = n + (float)KN * 1e-5f;
    #pragma unroll
    for (int j = 0; j < 4; j++) {
        int k = tid + j * 1024;
        g_cs[k] = (ncs[j] + 1e-5f) / denom * n;
    }
    if (tid == 0) out[O_LOSS] = 0.25f * (g_losssum / 2097152.0f);
}

// ---------------------------------------------------------------------------
// K5: new_ema_w and new_embedding
// ---------------------------------------------------------------------------
__global__ void k_fin2(const float* __restrict__ ema_w, float* __restrict__ out)
{
    int i = blockIdx.x * blockDim.x + threadIdx.x;   // 262144 total
    float nw = 0.99f * ema_w[i] + 0.01f * g_dw[i];
    out[O_NW + i] = nw;
    out[O_NE + i] = __fdiv_rn(nw, g_cs[i >> 6]);
}

// ---------------------------------------------------------------------------
#define SMA_BYTES 56832

extern "C" void kernel_launch(void* const* d_in, const int* in_sizes, int n_in,
                              void* d_out, int out_size)
{
    const float* z      = (const float*)d_in[0];
    const float* emb    = (const float*)d_in[1];
    const float* ema_cs = (const float*)d_in[2];
    const float* ema_w  = (const float*)d_in[3];
    float* out = (float*)d_out;

    cudaFuncSetAttribute(k_passA, cudaFuncAttributeMaxDynamicSharedMemorySize,
                         SMA_BYTES);

    k_prep    <<<256, 256>>>(z, emb);
    k_passA   <<<ABLK, 256, SMA_BYTES>>>();
    k_rescreen<<<512, 256>>>(z, emb);
    k_scatter <<<NROWS / 8, 256>>>(z, emb, out);
    k_fin1    <<<1, 1024>>>(ema_cs, out);
    k_fin2    <<<KN * DIM / 256, 256>>>(ema_w, out);
}

// round 8
// speedup vs baseline: 1.0385x; 1.0385x over previous
#include <cuda_runtime.h>
#include <cuda_bf16.h>
#include <cfloat>

// ---------------------------------------------------------------------------
// VectorQuantizer (VQ-VAE) fused pipeline, sm_100 (toolchain: no 'a' features,
// tcgen05 unavailable -> legacy mma.sync bf16, fragments proven in R6).
// R7 -> R8: fixed the R6 candidate flood:
//   - warm-start rowmin via exact 32-sample prepass (k_warm)
//   - per-chunk thresholds in registers, per-element epilogue = fmaf+fmin+cmp
//   - rare direct appends (no ballot, no per-element atomics)
// Correctness shell (margin-collect + exact reference-rounded rescreen,
// rel_err 6e-8 in R6) unchanged.
// ---------------------------------------------------------------------------

#define NROWS 32768
#define KN    4096
#define DIM   64

// pass A tiling
#define AM    128            // rows per CTA
#define ABLK  (NROWS / AM)   // 256 CTAs
#define ACH   128            // codes per chunk
#define NACH  (KN / ACH)     // 32
#define LDT   72             // smem tile row stride (halves): conflict-free ldmatrix
#define MARGIN 6e-4f
#define CAND_CAP (1u << 22)  // 4M candidate slots

// output offsets (elements)
#define O_ZQ   0
#define O_IND  2097152
#define O_LOSS 2129920
#define O_NE   2129921
#define O_NCS  2392065
#define O_NW   2396161

// scratch
__device__ float              g_zz[NROWS];
__device__ float              g_e2[KN];
__device__ float              g_rmin[NROWS];     // warm-start row min (exact, +slack)
__device__ float              g_counts[KN];
__device__ float              g_dw[KN * DIM];
__device__ float              g_cs[KN];
__device__ float              g_losssum;
__device__ unsigned long long g_best[NROWS];     // (v_bits<<32)|code
__device__ unsigned           g_cand[CAND_CAP];  // (row<<12)|code
__device__ unsigned           g_ncand;
__device__ __nv_bfloat16      g_zb[NROWS * DIM];
__device__ __nv_bfloat16      g_eb[KN * DIM];

__device__ __forceinline__ unsigned smem_u32(const void* p) {
    unsigned r;
    asm("{ .reg .u64 t; cvta.to.shared.u64 t, %1; cvt.u32.u64 %0, t; }"
        : "=r"(r) : "l"(p));
    return r;
}

#define MMA16816(c, A, B0, B1) \
    asm volatile("mma.sync.aligned.m16n8k16.row.col.f32.bf16.bf16.f32 " \
        "{%0,%1,%2,%3}, {%4,%5,%6,%7}, {%8,%9}, {%0,%1,%2,%3};" \
        : "+f"((c)[0]), "+f"((c)[1]), "+f"((c)[2]), "+f"((c)[3]) \
        : "r"((A)[0]), "r"((A)[1]), "r"((A)[2]), "r"((A)[3]), \
          "r"(B0), "r"(B1))

#define CP_ASYNC8(dst, src) \
    asm volatile("cp.async.ca.shared.global [%0], [%1], 8;" \
        :: "r"(dst), "l"(src))

// ---------------------------------------------------------------------------
// K0: zero scratch, init g_best/g_ncand, ||e||^2, ||z||^2 (exact reference
// rounding: sequential fadd_rn(fmul_rn)), bf16 copies of z and emb.
// ---------------------------------------------------------------------------
__global__ void k_prep(const float* __restrict__ z, const float* __restrict__ emb) {
    int i = blockIdx.x * blockDim.x + threadIdx.x;   // 65536 threads
    int stride = gridDim.x * blockDim.x;
    for (int j = i; j < KN * DIM; j += stride) {
        g_dw[j] = 0.f;
        g_eb[j] = __float2bfloat16(emb[j]);
    }
    for (int j = i; j < NROWS * DIM; j += stride)
        g_zb[j] = __float2bfloat16(z[j]);
    if (i < KN) {
        g_counts[i] = 0.f;
        const float* e = emb + (size_t)i * DIM;
        float s = 0.f;
        #pragma unroll
        for (int d = 0; d < DIM; d++) {
            float v = __ldg(e + d);
            s = __fadd_rn(s, __fmul_rn(v, v));
        }
        g_e2[i] = s;
    }
    if (i < NROWS) {
        g_best[i] = 0xFFFFFFFFFFFFFFFFull;
        const float* zr = z + (size_t)i * DIM;
        float s = 0.f;
        #pragma unroll
        for (int d = 0; d < DIM; d++) {
            float v = __ldg(zr + d);
            s = __fadd_rn(s, __fmul_rn(v, v));
        }
        g_zz[i] = s;
    }
    if (i == 0) { g_losssum = 0.f; g_ncand = 0u; }
}

// ---------------------------------------------------------------------------
// K0b: warm-start rowmin. Every row: exact fp32 s'=1+||e||^2-2 z.e over the
// SAME 32 sampled codes (smem-broadcast). +1e-4 slack covers exact-vs-bf16
// crossover at the threshold.
// ---------------------------------------------------------------------------
__global__ void k_warm(const float* __restrict__ z, const float* __restrict__ emb) {
    __shared__ float ec[32 * DIM];   // 8 KB sampled codes
    __shared__ float ee2[32];
    const int tid = threadIdx.x;     // 256
    for (int i = tid; i < 32 * DIM; i += 256) {
        int j = i >> 6, d = i & 63;
        ec[i] = __ldg(&emb[(size_t)(j * 128 + 64) * DIM + d]);
    }
    __syncthreads();
    if (tid < 32) {
        float s = 0.f;
        #pragma unroll
        for (int d = 0; d < DIM; d++) { float v = ec[tid * DIM + d]; s += v * v; }
        ee2[tid] = 1.0f + s;
    }
    __syncthreads();

    int row = blockIdx.x * 256 + tid;
    const float4* zr4 = (const float4*)(z + (size_t)row * DIM);
    float4 zl[16];
    #pragma unroll
    for (int q = 0; q < 16; q++) zl[q] = zr4[q];

    float best = FLT_MAX;
    #pragma unroll 4
    for (int j = 0; j < 32; j++) {
        const float4* e4 = (const float4*)(ec + j * DIM);
        float dot = 0.f;
        #pragma unroll
        for (int q = 0; q < 16; q++) {
            float4 e = e4[q];
            dot = fmaf(zl[q].x, e.x, dot);
            dot = fmaf(zl[q].y, e.y, dot);
            dot = fmaf(zl[q].z, e.z, dot);
            dot = fmaf(zl[q].w, e.w, dot);
        }
        best = fminf(best, fmaf(-2.f, dot, ee2[j]));
    }
    g_rmin[row] = best + 1e-4f;
}

// ---------------------------------------------------------------------------
// K1 (pass A): bf16 tensor-core distance scan + margin collection.
// 256 threads = 8 warps; warp_m = w>>1 (32 rows), warp_n = w&1 (64 codes).
// smem: zt[128][72]h, et[2][128][72]h (cp.async double buffer),
//       e2s[2][128]f (staged as e2+1 so s' > 0), rowmin[128]u (float bits).
// Epilogue: thresholds per chunk in regs; per element fmaf+fmin+cmp; rare
// direct global appends; 4 shared atomicMin per thread per chunk.
// ---------------------------------------------------------------------------
__global__ void __launch_bounds__(256, 2) k_passA() {
    extern __shared__ __align__(16) char smA[];
    __nv_bfloat16* zt = (__nv_bfloat16*)smA;                  // 9216 halves
    float*    e2s    = (float*)(smA + 55296);                 // 2*128 floats
    unsigned* rowmin = (unsigned*)(smA + 56320);              // 128

    const int tid  = threadIdx.x;
    const int lane = tid & 31;
    const int w    = tid >> 5;
    const int wm   = w >> 1;        // 0..3
    const int wn   = w & 1;         // 0..1
    const int gid  = lane >> 2;     // fragment row group
    const int qid  = lane & 3;      // fragment col pair
    const int r0   = blockIdx.x * AM;

    // ---- stage z tile (plain, once) ----
    const uint2* zb2 = (const uint2*)g_zb;
    #pragma unroll
    for (int it = 0; it < 8; it++) {
        int i  = tid + it * 256;       // 2048
        int r  = i >> 4;
        int c4 = i & 15;
        *(uint2*)(zt + r * LDT + c4 * 4) = zb2[(size_t)(r0 + r) * 16 + c4];
    }
    if (tid < AM) rowmin[tid] = __float_as_uint(__ldg(&g_rmin[r0 + tid]));

    // ---- prefetch e chunk 0 ----
    {
        unsigned etb = smem_u32(zt + 9216);
        const char* src0 = (const char*)g_eb;
        #pragma unroll
        for (int it = 0; it < 8; it++) {
            int i  = tid + it * 256;
            int r  = i >> 4;
            int c4 = i & 15;
            CP_ASYNC8(etb + (unsigned)(r * LDT + c4 * 4) * 2,
                      src0 + ((size_t)r * 64 + c4 * 4) * 2);
        }
        asm volatile("cp.async.commit_group;");
        if (tid < ACH) e2s[tid] = __ldg(&g_e2[tid]) + 1.0f;
    }
    __syncthreads();   // zt + rowmin visible

    // ---- A fragments (held across all chunks) ----
    unsigned a[2][4][4];
    {
        unsigned ztb = smem_u32(zt);
        #pragma unroll
        for (int tm = 0; tm < 2; tm++)
            #pragma unroll
            for (int kt = 0; kt < 4; kt++) {
                int R0 = wm * 32 + tm * 16;
                unsigned addr = ztb +
                    (unsigned)((R0 + (lane & 15)) * LDT + kt * 16 +
                               ((lane >> 4) << 3)) * 2;
                asm volatile(
                    "ldmatrix.sync.aligned.m8n8.x4.shared.b16 {%0,%1,%2,%3}, [%4];"
                    : "=r"(a[tm][kt][0]), "=r"(a[tm][kt][1]),
                      "=r"(a[tm][kt][2]), "=r"(a[tm][kt][3])
                    : "r"(addr));
            }
    }

    // thread's 4 row slots: slot = tm*2 + jh -> rl = wm*32 + tm*16 + gid + jh*8
    int rls[4];
    #pragma unroll
    for (int slot = 0; slot < 4; slot++)
        rls[slot] = wm * 32 + (slot >> 1) * 16 + gid + (slot & 1) * 8;

    for (int ch = 0; ch < NACH; ch++) {
        asm volatile("cp.async.wait_group 0;");
        __syncthreads();   // current et/e2s visible; prev epilogue done

        if (ch + 1 < NACH) {
            int nb2 = (ch + 1) & 1;
            unsigned etb = smem_u32(zt + 9216 + nb2 * 9216);
            const char* src = (const char*)g_eb +
                              (size_t)(ch + 1) * ACH * 64 * 2;
            #pragma unroll
            for (int it = 0; it < 8; it++) {
                int i  = tid + it * 256;
                int r  = i >> 4;
                int c4 = i & 15;
                CP_ASYNC8(etb + (unsigned)(r * LDT + c4 * 4) * 2,
                          src + ((size_t)r * 64 + c4 * 4) * 2);
            }
            asm volatile("cp.async.commit_group;");
            if (tid < ACH)
                e2s[nb2 * ACH + tid] = __ldg(&g_e2[(ch + 1) * ACH + tid]) + 1.0f;
        }

        // per-chunk thresholds (stale-read safe: only over-collects)
        float thr[4], lmin[4];
        #pragma unroll
        for (int slot = 0; slot < 4; slot++) {
            thr[slot]  = __uint_as_float(rowmin[rls[slot]]) + MARGIN;
            lmin[slot] = FLT_MAX;
        }

        const int cb = ch & 1;
        unsigned et_base = smem_u32(zt + 9216 + cb * 9216);
        const float* e2c = e2s + cb * ACH;

        #pragma unroll
        for (int nt = 0; nt < 8; nt++) {
            const int nb = wn * 64 + nt * 8;

            unsigned b0[4], b1[4];
            #pragma unroll
            for (int kt = 0; kt < 4; kt++) {
                unsigned addr = et_base +
                    (unsigned)((nb + (lane & 7)) * LDT + kt * 16 +
                               (((lane >> 3) & 1) << 3)) * 2;
                asm volatile(
                    "ldmatrix.sync.aligned.m8n8.x2.shared.b16 {%0,%1}, [%2];"
                    : "=r"(b0[kt]), "=r"(b1[kt]) : "r"(addr));
            }

            float c0[4] = {0.f, 0.f, 0.f, 0.f};
            float c1[4] = {0.f, 0.f, 0.f, 0.f};
            #pragma unroll
            for (int kt = 0; kt < 4; kt++) {
                MMA16816(c0, a[0][kt], b0[kt], b1[kt]);
                MMA16816(c1, a[1][kt], b0[kt], b1[kt]);
            }

            const float e2p0 = e2c[nb + qid * 2];
            const float e2p1 = e2c[nb + qid * 2 + 1];

            #pragma unroll
            for (int tm = 0; tm < 2; tm++) {
                const float* cc = tm ? c1 : c0;
                #pragma unroll
                for (int j = 0; j < 4; j++) {
                    float s = fmaf(-2.f, cc[j], (j & 1) ? e2p1 : e2p0);
                    int slot = tm * 2 + (j >> 1);
                    lmin[slot] = fminf(lmin[slot], s);
                    if (s <= thr[slot]) {                       // rare
                        unsigned pos = atomicAdd(&g_ncand, 1u);
                        unsigned code = (unsigned)(ch * ACH + nb +
                                                   qid * 2 + (j & 1));
                        if (pos < CAND_CAP)
                            g_cand[pos] =
                                ((unsigned)(r0 + rls[slot]) << 12) | code;
                    }
                }
            }
        }

        // fold chunk minima into shared rowmin (visible next chunk via sync)
        #pragma unroll
        for (int slot = 0; slot < 4; slot++)
            atomicMin(&rowmin[rls[slot]], __float_as_uint(lmin[slot]));
    }
}

// ---------------------------------------------------------------------------
// K2 (pass B): exact reference-rounded rescreen of collected candidates.
// v = fsub_rn(fadd_rn(zz, ee), 2*dot), dot = sequential fp32 FMA chain
// (R3/R4-proven). Winner per row: atomicMin on (v_bits<<32)|code -> exact
// value order + lowest-index tie-break. v ~ 64 > 0, so uint order == float.
// ---------------------------------------------------------------------------
__global__ void k_rescreen(const float* __restrict__ z,
                           const float* __restrict__ emb) {
    unsigned n = g_ncand;
    if (n > CAND_CAP) n = CAND_CAP;
    for (unsigned i = blockIdx.x * blockDim.x + threadIdx.x; i < n;
         i += gridDim.x * blockDim.x) {
        unsigned cd = g_cand[i];
        int row  = (int)(cd >> 12);
        int code = (int)(cd & 4095u);
        const float* zr = z   + (size_t)row  * DIM;
        const float* er = emb + (size_t)code * DIM;
        float acc = 0.f;
        #pragma unroll
        for (int d = 0; d < DIM; d++)
            acc = __fmaf_rn(zr[d], __ldg(er + d), acc);
        float v = __fsub_rn(__fadd_rn(g_zz[row], g_e2[code]),
                            __fmul_rn(2.f, acc));
        unsigned long long key =
            ((unsigned long long)__float_as_uint(v) << 32) | (unsigned)code;
        atomicMin(&g_best[row], key);
    }
}

// ---------------------------------------------------------------------------
// K3: gather z_q, straight-through output, loss partial, scatter counts/dw.
// ---------------------------------------------------------------------------
__global__ void k_scatter(const float* __restrict__ z, const float* __restrict__ emb,
                          float* __restrict__ out)
{
    int row = blockIdx.x * 8 + (threadIdx.x >> 5);
    int ln  = threadIdx.x & 31;
    int idx = (int)(unsigned)(g_best[row] & 0xffffffffull);
    const float* zr = z   + (size_t)row * DIM;
    const float* er = emb + (size_t)idx * DIM;
    float* zq = out + O_ZQ + (size_t)row * DIM;
    float l = 0.f;
    #pragma unroll
    for (int t = 0; t < 2; t++) {
        int j = ln + 32 * t;
        float zv = zr[j], ev = __ldg(er + j);
        zq[j] = __fadd_rn(zv, __fsub_rn(ev, zv));
        float dd = __fsub_rn(zv, ev);
        l += dd * dd;
        atomicAdd(&g_dw[idx * DIM + j], zv);
    }
    if (ln == 0) {
        atomicAdd(&g_counts[idx], 1.f);
        out[O_IND + row] = (float)idx;
    }
    #pragma unroll
    for (int o = 16; o; o >>= 1) l += __shfl_xor_sync(0xffffffffu, l, o);
    __shared__ float sl[8];
    if (ln == 0) sl[threadIdx.x >> 5] = l;
    __syncthreads();
    if (threadIdx.x == 0) {
        float s = 0.f;
        #pragma unroll
        for (int w2 = 0; w2 < 8; w2++) s += sl[w2];
        atomicAdd(&g_losssum, s);
    }
}

// ---------------------------------------------------------------------------
// K4: new_cluster_size, n, normalized cluster size, loss (single block)
// ---------------------------------------------------------------------------
__global__ void k_fin1(const float* __restrict__ ema_cs, float* __restrict__ out)
{
    int tid = threadIdx.x;  // 1024
    float ncs[4];
    float s = 0.f;
    #pragma unroll
    for (int j = 0; j < 4; j++) {
        int k = tid + j * 1024;
        float v = 0.99f * ema_cs[k] + 0.01f * g_counts[k];
        ncs[j] = v; s += v;
        out[O_NCS + k] = v;
    }
    __shared__ float sp[32];
    #pragma unroll
    for (int o = 16; o; o >>= 1) s += __shfl_xor_sync(0xffffffffu, s, o);
    if ((tid & 31) == 0) sp[tid >> 5] = s;
    __syncthreads();
    if (tid < 32) {
        float v = sp[tid];
        #pragma unroll
        for (int o = 16; o; o >>= 1) v += __shfl_xor_sync(0xffffffffu, v, o);
        if (tid == 0) sp[0] = v;
    }
    __syncthreads();
    float n = sp[0];
    float denom = n + (float)KN * 1e-5f;
    #pragma unroll
    for (int j = 0; j < 4; j++) {
        int k = tid + j * 1024;
        g_cs[k] = (ncs[j] + 1e-5f) / denom * n;
    }
    if (tid == 0) out[O_LOSS] = 0.25f * (g_losssum / 2097152.0f);
}

// ---------------------------------------------------------------------------
// K5: new_ema_w and new_embedding
// ---------------------------------------------------------------------------
__global__ void k_fin2(const float* __restrict__ ema_w, float* __restrict__ out)
{
    int i = blockIdx.x * blockDim.x + threadIdx.x;   // 262144 total
    float nw = 0.99f * ema_w[i] + 0.01f * g_dw[i];
    out[O_NW + i] = nw;
    out[O_NE + i] = __fdiv_rn(nw, g_cs[i >> 6]);
}

// ---------------------------------------------------------------------------
#define SMA_BYTES 56832

extern "C" void kernel_launch(void* const* d_in, const int* in_sizes, int n_in,
                              void* d_out, int out_size)
{
    const float* z      = (const float*)d_in[0];
    const float* emb    = (const float*)d_in[1];
    const float* ema_cs = (const float*)d_in[2];
    const float* ema_w  = (const float*)d_in[3];
    float* out = (float*)d_out;

    cudaFuncSetAttribute(k_passA, cudaFuncAttributeMaxDynamicSharedMemorySize,
                         SMA_BYTES);

    k_prep    <<<256, 256>>>(z, emb);
    k_warm    <<<NROWS / 256, 256>>>(z, emb);
    k_passA   <<<ABLK, 256, SMA_BYTES>>>();
    k_rescreen<<<512, 256>>>(z, emb);
    k_scatter <<<NROWS / 8, 256>>>(z, emb, out);
    k_fin1    <<<1, 1024>>>(ema_cs, out);
    k_fin2    <<<KN * DIM / 256, 256>>>(ema_w, out);
}

// round 9
// speedup vs baseline: 1.4280x; 1.3751x over previous
#include <cuda_runtime.h>
#include <cuda_bf16.h>
#include <cfloat>

// ---------------------------------------------------------------------------
// VectorQuantizer (VQ-VAE) fused pipeline, sm_100 (no 'a' features available
// to ptxas -> legacy mma.sync bf16).
// R8 -> R9: k_rescreen rewritten warp-per-candidate (coalesced row reads,
// shuffle-reduced dot). R8's divergent per-thread row walk caused 32-way
// wavefront replay (L1 81.7%, 236 us). Everything else byte-identical to R8
// (passed, rel_err 6e-7).
// ---------------------------------------------------------------------------

#define NROWS 32768
#define KN    4096
#define DIM   64

// pass A tiling
#define AM    128            // rows per CTA
#define ABLK  (NROWS / AM)   // 256 CTAs
#define ACH   128            // codes per chunk
#define NACH  (KN / ACH)     // 32
#define LDT   72             // smem tile row stride (halves): conflict-free ldmatrix
#define MARGIN 6e-4f
#define CAND_CAP (1u << 22)  // 4M candidate slots

// output offsets (elements)
#define O_ZQ   0
#define O_IND  2097152
#define O_LOSS 2129920
#define O_NE   2129921
#define O_NCS  2392065
#define O_NW   2396161

// scratch
__device__ float              g_zz[NROWS];
__device__ float              g_e2[KN];
__device__ float              g_rmin[NROWS];     // warm-start row min (exact, +slack)
__device__ float              g_counts[KN];
__device__ float              g_dw[KN * DIM];
__device__ float              g_cs[KN];
__device__ float              g_losssum;
__device__ unsigned long long g_best[NROWS];     // (v_bits<<32)|code
__device__ unsigned           g_cand[CAND_CAP];  // (row<<12)|code
__device__ unsigned           g_ncand;
__device__ __nv_bfloat16      g_zb[NROWS * DIM];
__device__ __nv_bfloat16      g_eb[KN * DIM];

__device__ __forceinline__ unsigned smem_u32(const void* p) {
    unsigned r;
    asm("{ .reg .u64 t; cvta.to.shared.u64 t, %1; cvt.u32.u64 %0, t; }"
        : "=r"(r) : "l"(p));
    return r;
}

#define MMA16816(c, A, B0, B1) \
    asm volatile("mma.sync.aligned.m16n8k16.row.col.f32.bf16.bf16.f32 " \
        "{%0,%1,%2,%3}, {%4,%5,%6,%7}, {%8,%9}, {%0,%1,%2,%3};" \
        : "+f"((c)[0]), "+f"((c)[1]), "+f"((c)[2]), "+f"((c)[3]) \
        : "r"((A)[0]), "r"((A)[1]), "r"((A)[2]), "r"((A)[3]), \
          "r"(B0), "r"(B1))

#define CP_ASYNC8(dst, src) \
    asm volatile("cp.async.ca.shared.global [%0], [%1], 8;" \
        :: "r"(dst), "l"(src))

// ---------------------------------------------------------------------------
// K0: zero scratch, init g_best/g_ncand, ||e||^2, ||z||^2 (exact reference
// rounding: sequential fadd_rn(fmul_rn)), bf16 copies of z and emb.
// ---------------------------------------------------------------------------
__global__ void k_prep(const float* __restrict__ z, const float* __restrict__ emb) {
    int i = blockIdx.x * blockDim.x + threadIdx.x;   // 65536 threads
    int stride = gridDim.x * blockDim.x;
    for (int j = i; j < KN * DIM; j += stride) {
        g_dw[j] = 0.f;
        g_eb[j] = __float2bfloat16(emb[j]);
    }
    for (int j = i; j < NROWS * DIM; j += stride)
        g_zb[j] = __float2bfloat16(z[j]);
    if (i < KN) {
        g_counts[i] = 0.f;
        const float* e = emb + (size_t)i * DIM;
        float s = 0.f;
        #pragma unroll
        for (int d = 0; d < DIM; d++) {
            float v = __ldg(e + d);
            s = __fadd_rn(s, __fmul_rn(v, v));
        }
        g_e2[i] = s;
    }
    if (i < NROWS) {
        g_best[i] = 0xFFFFFFFFFFFFFFFFull;
        const float* zr = z + (size_t)i * DIM;
        float s = 0.f;
        #pragma unroll
        for (int d = 0; d < DIM; d++) {
            float v = __ldg(zr + d);
            s = __fadd_rn(s, __fmul_rn(v, v));
        }
        g_zz[i] = s;
    }
    if (i == 0) { g_losssum = 0.f; g_ncand = 0u; }
}

// ---------------------------------------------------------------------------
// K0b: warm-start rowmin. Every row: exact fp32 s'=1+||e||^2-2 z.e over the
// SAME 32 sampled codes (smem-broadcast). +1e-4 slack covers exact-vs-bf16
// crossover at the threshold.
// ---------------------------------------------------------------------------
__global__ void k_warm(const float* __restrict__ z, const float* __restrict__ emb) {
    __shared__ float ec[32 * DIM];   // 8 KB sampled codes
    __shared__ float ee2[32];
    const int tid = threadIdx.x;     // 256
    for (int i = tid; i < 32 * DIM; i += 256) {
        int j = i >> 6, d = i & 63;
        ec[i] = __ldg(&emb[(size_t)(j * 128 + 64) * DIM + d]);
    }
    __syncthreads();
    if (tid < 32) {
        float s = 0.f;
        #pragma unroll
        for (int d = 0; d < DIM; d++) { float v = ec[tid * DIM + d]; s += v * v; }
        ee2[tid] = 1.0f + s;
    }
    __syncthreads();

    int row = blockIdx.x * 256 + tid;
    const float4* zr4 = (const float4*)(z + (size_t)row * DIM);
    float4 zl[16];
    #pragma unroll
    for (int q = 0; q < 16; q++) zl[q] = zr4[q];

    float best = FLT_MAX;
    #pragma unroll 4
    for (int j = 0; j < 32; j++) {
        const float4* e4 = (const float4*)(ec + j * DIM);
        float dot = 0.f;
        #pragma unroll
        for (int q = 0; q < 16; q++) {
            float4 e = e4[q];
            dot = fmaf(zl[q].x, e.x, dot);
            dot = fmaf(zl[q].y, e.y, dot);
            dot = fmaf(zl[q].z, e.z, dot);
            dot = fmaf(zl[q].w, e.w, dot);
        }
        best = fminf(best, fmaf(-2.f, dot, ee2[j]));
    }
    g_rmin[row] = best + 1e-4f;
}

// ---------------------------------------------------------------------------
// K1 (pass A): bf16 tensor-core distance scan + margin collection.
// 256 threads = 8 warps; warp_m = w>>1 (32 rows), warp_n = w&1 (64 codes).
// smem: zt[128][72]h, et[2][128][72]h (cp.async double buffer),
//       e2s[2][128]f (staged as e2+1 so s' > 0), rowmin[128]u (float bits).
// Epilogue: thresholds per chunk in regs; per element fmaf+fmin+cmp; rare
// direct global appends; 4 shared atomicMin per thread per chunk.
// ---------------------------------------------------------------------------
__global__ void __launch_bounds__(256, 2) k_passA() {
    extern __shared__ __align__(16) char smA[];
    __nv_bfloat16* zt = (__nv_bfloat16*)smA;                  // 9216 halves
    float*    e2s    = (float*)(smA + 55296);                 // 2*128 floats
    unsigned* rowmin = (unsigned*)(smA + 56320);              // 128

    const int tid  = threadIdx.x;
    const int lane = tid & 31;
    const int w    = tid >> 5;
    const int wm   = w >> 1;        // 0..3
    const int wn   = w & 1;         // 0..1
    const int gid  = lane >> 2;     // fragment row group
    const int qid  = lane & 3;      // fragment col pair
    const int r0   = blockIdx.x * AM;

    // ---- stage z tile (plain, once) ----
    const uint2* zb2 = (const uint2*)g_zb;
    #pragma unroll
    for (int it = 0; it < 8; it++) {
        int i  = tid + it * 256;       // 2048
        int r  = i >> 4;
        int c4 = i & 15;
        *(uint2*)(zt + r * LDT + c4 * 4) = zb2[(size_t)(r0 + r) * 16 + c4];
    }
    if (tid < AM) rowmin[tid] = __float_as_uint(__ldg(&g_rmin[r0 + tid]));

    // ---- prefetch e chunk 0 ----
    {
        unsigned etb = smem_u32(zt + 9216);
        const char* src0 = (const char*)g_eb;
        #pragma unroll
        for (int it = 0; it < 8; it++) {
            int i  = tid + it * 256;
            int r  = i >> 4;
            int c4 = i & 15;
            CP_ASYNC8(etb + (unsigned)(r * LDT + c4 * 4) * 2,
                      src0 + ((size_t)r * 64 + c4 * 4) * 2);
        }
        asm volatile("cp.async.commit_group;");
        if (tid < ACH) e2s[tid] = __ldg(&g_e2[tid]) + 1.0f;
    }
    __syncthreads();   // zt + rowmin visible

    // ---- A fragments (held across all chunks) ----
    unsigned a[2][4][4];
    {
        unsigned ztb = smem_u32(zt);
        #pragma unroll
        for (int tm = 0; tm < 2; tm++)
            #pragma unroll
            for (int kt = 0; kt < 4; kt++) {
                int R0 = wm * 32 + tm * 16;
                unsigned addr = ztb +
                    (unsigned)((R0 + (lane & 15)) * LDT + kt * 16 +
                               ((lane >> 4) << 3)) * 2;
                asm volatile(
                    "ldmatrix.sync.aligned.m8n8.x4.shared.b16 {%0,%1,%2,%3}, [%4];"
                    : "=r"(a[tm][kt][0]), "=r"(a[tm][kt][1]),
                      "=r"(a[tm][kt][2]), "=r"(a[tm][kt][3])
                    : "r"(addr));
            }
    }

    // thread's 4 row slots: slot = tm*2 + jh -> rl = wm*32 + tm*16 + gid + jh*8
    int rls[4];
    #pragma unroll
    for (int slot = 0; slot < 4; slot++)
        rls[slot] = wm * 32 + (slot >> 1) * 16 + gid + (slot & 1) * 8;

    for (int ch = 0; ch < NACH; ch++) {
        asm volatile("cp.async.wait_group 0;");
        __syncthreads();   // current et/e2s visible; prev epilogue done

        if (ch + 1 < NACH) {
            int nb2 = (ch + 1) & 1;
            unsigned etb = smem_u32(zt + 9216 + nb2 * 9216);
            const char* src = (const char*)g_eb +
                              (size_t)(ch + 1) * ACH * 64 * 2;
            #pragma unroll
            for (int it = 0; it < 8; it++) {
                int i  = tid + it * 256;
                int r  = i >> 4;
                int c4 = i & 15;
                CP_ASYNC8(etb + (unsigned)(r * LDT + c4 * 4) * 2,
                          src + ((size_t)r * 64 + c4 * 4) * 2);
            }
            asm volatile("cp.async.commit_group;");
            if (tid < ACH)
                e2s[nb2 * ACH + tid] = __ldg(&g_e2[(ch + 1) * ACH + tid]) + 1.0f;
        }

        // per-chunk thresholds (stale-read safe: only over-collects)
        float thr[4], lmin[4];
        #pragma unroll
        for (int slot = 0; slot < 4; slot++) {
            thr[slot]  = __uint_as_float(rowmin[rls[slot]]) + MARGIN;
            lmin[slot] = FLT_MAX;
        }

        const int cb = ch & 1;
        unsigned et_base = smem_u32(zt + 9216 + cb * 9216);
        const float* e2c = e2s + cb * ACH;

        #pragma unroll
        for (int nt = 0; nt < 8; nt++) {
            const int nb = wn * 64 + nt * 8;

            unsigned b0[4], b1[4];
            #pragma unroll
            for (int kt = 0; kt < 4; kt++) {
                unsigned addr = et_base +
                    (unsigned)((nb + (lane & 7)) * LDT + kt * 16 +
                               (((lane >> 3) & 1) << 3)) * 2;
                asm volatile(
                    "ldmatrix.sync.aligned.m8n8.x2.shared.b16 {%0,%1}, [%2];"
                    : "=r"(b0[kt]), "=r"(b1[kt]) : "r"(addr));
            }

            float c0[4] = {0.f, 0.f, 0.f, 0.f};
            float c1[4] = {0.f, 0.f, 0.f, 0.f};
            #pragma unroll
            for (int kt = 0; kt < 4; kt++) {
                MMA16816(c0, a[0][kt], b0[kt], b1[kt]);
                MMA16816(c1, a[1][kt], b0[kt], b1[kt]);
            }

            const float e2p0 = e2c[nb + qid * 2];
            const float e2p1 = e2c[nb + qid * 2 + 1];

            #pragma unroll
            for (int tm = 0; tm < 2; tm++) {
                const float* cc = tm ? c1 : c0;
                #pragma unroll
                for (int j = 0; j < 4; j++) {
                    float s = fmaf(-2.f, cc[j], (j & 1) ? e2p1 : e2p0);
                    int slot = tm * 2 + (j >> 1);
                    lmin[slot] = fminf(lmin[slot], s);
                    if (s <= thr[slot]) {                       // rare
                        unsigned pos = atomicAdd(&g_ncand, 1u);
                        unsigned code = (unsigned)(ch * ACH + nb +
                                                   qid * 2 + (j & 1));
                        if (pos < CAND_CAP)
                            g_cand[pos] =
                                ((unsigned)(r0 + rls[slot]) << 12) | code;
                    }
                }
            }
        }

        // fold chunk minima into shared rowmin (visible next chunk via sync)
        #pragma unroll
        for (int slot = 0; slot < 4; slot++)
            atomicMin(&rowmin[rls[slot]], __float_as_uint(lmin[slot]));
    }
}

// ---------------------------------------------------------------------------
// K2 (pass B): exact reference-rounded rescreen, WARP-PER-CANDIDATE.
// Lanes read z[row][ln], z[row][ln+32], e[code][ln], e[code][ln+32]
// (4 coalesced 128B lines/candidate vs 128 divergent in R8). Dot via
// 2 FMA + shuffle tree; error ~5e-10 << the ulp(64)~7.6e-6 grid of the
// final fsub_rn(fadd_rn(zz,ee), 2*dot) that decides ties (same grid
// argument validated R3-R8). Winner: atomicMin on (v_bits<<32)|code.
// ---------------------------------------------------------------------------
__global__ void k_rescreen(const float* __restrict__ z,
                           const float* __restrict__ emb) {
    unsigned n = g_ncand;
    if (n > CAND_CAP) n = CAND_CAP;
    const unsigned gw = (blockIdx.x * blockDim.x + threadIdx.x) >> 5;
    const unsigned nw = (gridDim.x * blockDim.x) >> 5;
    const int ln = threadIdx.x & 31;
    for (unsigned i = gw; i < n; i += nw) {
        unsigned cd = __ldg(&g_cand[i]);
        unsigned row  = cd >> 12;
        unsigned code = cd & 4095u;
        const float* zr = z   + (size_t)row  * DIM;
        const float* er = emb + (size_t)code * DIM;
        float z0 = __ldg(zr + ln), z1 = __ldg(zr + 32 + ln);
        float e0 = __ldg(er + ln), e1 = __ldg(er + 32 + ln);
        float p = __fmaf_rn(z1, e1, __fmul_rn(z0, e0));
        #pragma unroll
        for (int o = 16; o; o >>= 1)
            p += __shfl_xor_sync(0xffffffffu, p, o);
        if (ln == 0) {
            float v = __fsub_rn(__fadd_rn(__ldg(&g_zz[row]), __ldg(&g_e2[code])),
                                __fmul_rn(2.f, p));
            unsigned long long key =
                ((unsigned long long)__float_as_uint(v) << 32) | code;
            atomicMin(&g_best[row], key);
        }
    }
}

// ---------------------------------------------------------------------------
// K3: gather z_q, straight-through output, loss partial, scatter counts/dw.
// ---------------------------------------------------------------------------
__global__ void k_scatter(const float* __restrict__ z, const float* __restrict__ emb,
                          float* __restrict__ out)
{
    int row = blockIdx.x * 8 + (threadIdx.x >> 5);
    int ln  = threadIdx.x & 31;
    int idx = (int)(unsigned)(g_best[row] & 0xffffffffull);
    const float* zr = z   + (size_t)row * DIM;
    const float* er = emb + (size_t)idx * DIM;
    float* zq = out + O_ZQ + (size_t)row * DIM;
    float l = 0.f;
    #pragma unroll
    for (int t = 0; t < 2; t++) {
        int j = ln + 32 * t;
        float zv = zr[j], ev = __ldg(er + j);
        zq[j] = __fadd_rn(zv, __fsub_rn(ev, zv));
        float dd = __fsub_rn(zv, ev);
        l += dd * dd;
        atomicAdd(&g_dw[idx * DIM + j], zv);
    }
    if (ln == 0) {
        atomicAdd(&g_counts[idx], 1.f);
        out[O_IND + row] = (float)idx;
    }
    #pragma unroll
    for (int o = 16; o; o >>= 1) l += __shfl_xor_sync(0xffffffffu, l, o);
    __shared__ float sl[8];
    if (ln == 0) sl[threadIdx.x >> 5] = l;
    __syncthreads();
    if (threadIdx.x == 0) {
        float s = 0.f;
        #pragma unroll
        for (int w2 = 0; w2 < 8; w2++) s += sl[w2];
        atomicAdd(&g_losssum, s);
    }
}

// ---------------------------------------------------------------------------
// K4: new_cluster_size, n, normalized cluster size, loss (single block)
// ---------------------------------------------------------------------------
__global__ void k_fin1(const float* __restrict__ ema_cs, float* __restrict__ out)
{
    int tid = threadIdx.x;  // 1024
    float ncs[4];
    float s = 0.f;
    #pragma unroll
    for (int j = 0; j < 4; j++) {
        int k = tid + j * 1024;
        float v = 0.99f * ema_cs[k] + 0.01f * g_counts[k];
        ncs[j] = v; s += v;
        out[O_NCS + k] = v;
    }
    __shared__ float sp[32];
    #pragma unroll
    for (int o = 16; o; o >>= 1) s += __shfl_xor_sync(0xffffffffu, s, o);
    if ((tid & 31) == 0) sp[tid >> 5] = s;
    __syncthreads();
    if (tid < 32) {
        float v = sp[tid];
        #pragma unroll
        for (int o = 16; o; o >>= 1) v += __shfl_xor_sync(0xffffffffu, v, o);
        if (tid == 0) sp[0] = v;
    }
    __syncthreads();
    float n = sp[0];
    float denom = n + (float)KN * 1e-5f;
    #pragma unroll
    for (int j = 0; j < 4; j++) {
        int k = tid + j * 1024;
        g_cs[k] = (ncs[j] + 1e-5f) / denom * n;
    }
    if (tid == 0) out[O_LOSS] = 0.25f * (g_losssum / 2097152.0f);
}

// ---------------------------------------------------------------------------
// K5: new_ema_w and new_embedding
// ---------------------------------------------------------------------------
__global__ void k_fin2(const float* __restrict__ ema_w, float* __restrict__ out)
{
    int i = blockIdx.x * blockDim.x + threadIdx.x;   // 262144 total
    float nw = 0.99f * ema_w[i] + 0.01f * g_dw[i];
    out[O_NW + i] = nw;
    out[O_NE + i] = __fdiv_rn(nw, g_cs[i >> 6]);
}

// ---------------------------------------------------------------------------
#define SMA_BYTES 56832

extern "C" void kernel_launch(void* const* d_in, const int* in_sizes, int n_in,
                              void* d_out, int out_size)
{
    const float* z      = (const float*)d_in[0];
    const float* emb    = (const float*)d_in[1];
    const float* ema_cs = (const float*)d_in[2];
    const float* ema_w  = (const float*)d_in[3];
    float* out = (float*)d_out;

    cudaFuncSetAttribute(k_passA, cudaFuncAttributeMaxDynamicSharedMemorySize,
                         SMA_BYTES);

    k_prep    <<<256, 256>>>(z, emb);
    k_warm    <<<NROWS / 256, 256>>>(z, emb);
    k_passA   <<<ABLK, 256, SMA_BYTES>>>();
    k_rescreen<<<512, 256>>>(z, emb);
    k_scatter <<<NROWS / 8, 256>>>(z, emb, out);
    k_fin1    <<<1, 1024>>>(ema_cs, out);
    k_fin2    <<<KN * DIM / 256, 256>>>(ema_w, out);
}

// round 10
// speedup vs baseline: 1.6167x; 1.1321x over previous
#include <cuda_runtime.h>
#include <cuda_bf16.h>
#include <cfloat>

// ---------------------------------------------------------------------------
// VectorQuantizer (VQ-VAE) fused pipeline, sm_100 (no 'a' features for ptxas
// -> legacy mma.sync bf16).
// R9 -> R10:
//   - k_rescreen: 8 lanes per candidate (4/warp), 3-deep shuffle, grid 1024
//     (R9 was latency-bound: 1 candidate/warp, 5-deep 26-cyc shuffles)
//   - k_passA: occupancy 2->3 CTAs/SM; pairwise-compare epilogue
// Correctness shell unchanged (R9: rel_err 5.95e-7, bit-identical to R8).
// ---------------------------------------------------------------------------

#define NROWS 32768
#define KN    4096
#define DIM   64

// pass A tiling
#define AM    128            // rows per CTA
#define ABLK  (NROWS / AM)   // 256 CTAs
#define ACH   128            // codes per chunk
#define NACH  (KN / ACH)     // 32
#define LDT   72             // smem tile row stride (halves): conflict-free ldmatrix
#define MARGIN 6e-4f
#define CAND_CAP (1u << 22)  // 4M candidate slots

// output offsets (elements)
#define O_ZQ   0
#define O_IND  2097152
#define O_LOSS 2129920
#define O_NE   2129921
#define O_NCS  2392065
#define O_NW   2396161

// scratch
__device__ float              g_zz[NROWS];
__device__ float              g_e2[KN];
__device__ float              g_rmin[NROWS];     // warm-start row min (exact, +slack)
__device__ float              g_counts[KN];
__device__ float              g_dw[KN * DIM];
__device__ float              g_cs[KN];
__device__ float              g_losssum;
__device__ unsigned long long g_best[NROWS];     // (v_bits<<32)|code
__device__ unsigned           g_cand[CAND_CAP];  // (row<<12)|code
__device__ unsigned           g_ncand;
__device__ __nv_bfloat16      g_zb[NROWS * DIM];
__device__ __nv_bfloat16      g_eb[KN * DIM];

__device__ __forceinline__ unsigned smem_u32(const void* p) {
    unsigned r;
    asm("{ .reg .u64 t; cvta.to.shared.u64 t, %1; cvt.u32.u64 %0, t; }"
        : "=r"(r) : "l"(p));
    return r;
}

#define MMA16816(c, A, B0, B1) \
    asm volatile("mma.sync.aligned.m16n8k16.row.col.f32.bf16.bf16.f32 " \
        "{%0,%1,%2,%3}, {%4,%5,%6,%7}, {%8,%9}, {%0,%1,%2,%3};" \
        : "+f"((c)[0]), "+f"((c)[1]), "+f"((c)[2]), "+f"((c)[3]) \
        : "r"((A)[0]), "r"((A)[1]), "r"((A)[2]), "r"((A)[3]), \
          "r"(B0), "r"(B1))

#define CP_ASYNC8(dst, src) \
    asm volatile("cp.async.ca.shared.global [%0], [%1], 8;" \
        :: "r"(dst), "l"(src))

// ---------------------------------------------------------------------------
// K0: zero scratch, init g_best/g_ncand, ||e||^2, ||z||^2 (exact reference
// rounding: sequential fadd_rn(fmul_rn)), bf16 copies of z and emb.
// ---------------------------------------------------------------------------
__global__ void k_prep(const float* __restrict__ z, const float* __restrict__ emb) {
    int i = blockIdx.x * blockDim.x + threadIdx.x;   // 65536 threads
    int stride = gridDim.x * blockDim.x;
    for (int j = i; j < KN * DIM; j += stride) {
        g_dw[j] = 0.f;
        g_eb[j] = __float2bfloat16(emb[j]);
    }
    for (int j = i; j < NROWS * DIM; j += stride)
        g_zb[j] = __float2bfloat16(z[j]);
    if (i < KN) {
        g_counts[i] = 0.f;
        const float* e = emb + (size_t)i * DIM;
        float s = 0.f;
        #pragma unroll
        for (int d = 0; d < DIM; d++) {
            float v = __ldg(e + d);
            s = __fadd_rn(s, __fmul_rn(v, v));
        }
        g_e2[i] = s;
    }
    if (i < NROWS) {
        g_best[i] = 0xFFFFFFFFFFFFFFFFull;
        const float* zr = z + (size_t)i * DIM;
        float s = 0.f;
        #pragma unroll
        for (int d = 0; d < DIM; d++) {
            float v = __ldg(zr + d);
            s = __fadd_rn(s, __fmul_rn(v, v));
        }
        g_zz[i] = s;
    }
    if (i == 0) { g_losssum = 0.f; g_ncand = 0u; }
}

// ---------------------------------------------------------------------------
// K0b: warm-start rowmin. Every row: exact fp32 s'=1+||e||^2-2 z.e over the
// SAME 32 sampled codes (smem-broadcast). +1e-4 slack covers exact-vs-bf16
// crossover at the threshold.
// ---------------------------------------------------------------------------
__global__ void k_warm(const float* __restrict__ z, const float* __restrict__ emb) {
    __shared__ float ec[32 * DIM];   // 8 KB sampled codes
    __shared__ float ee2[32];
    const int tid = threadIdx.x;     // 256
    for (int i = tid; i < 32 * DIM; i += 256) {
        int j = i >> 6, d = i & 63;
        ec[i] = __ldg(&emb[(size_t)(j * 128 + 64) * DIM + d]);
    }
    __syncthreads();
    if (tid < 32) {
        float s = 0.f;
        #pragma unroll
        for (int d = 0; d < DIM; d++) { float v = ec[tid * DIM + d]; s += v * v; }
        ee2[tid] = 1.0f + s;
    }
    __syncthreads();

    int row = blockIdx.x * 256 + tid;
    const float4* zr4 = (const float4*)(z + (size_t)row * DIM);
    float4 zl[16];
    #pragma unroll
    for (int q = 0; q < 16; q++) zl[q] = zr4[q];

    float best = FLT_MAX;
    #pragma unroll 4
    for (int j = 0; j < 32; j++) {
        const float4* e4 = (const float4*)(ec + j * DIM);
        float dot = 0.f;
        #pragma unroll
        for (int q = 0; q < 16; q++) {
            float4 e = e4[q];
            dot = fmaf(zl[q].x, e.x, dot);
            dot = fmaf(zl[q].y, e.y, dot);
            dot = fmaf(zl[q].z, e.z, dot);
            dot = fmaf(zl[q].w, e.w, dot);
        }
        best = fminf(best, fmaf(-2.f, dot, ee2[j]));
    }
    g_rmin[row] = best + 1e-4f;
}

// ---------------------------------------------------------------------------
// K1 (pass A): bf16 tensor-core distance scan + margin collection.
// 256 threads = 8 warps; warp_m = w>>1 (32 rows), warp_n = w&1 (64 codes).
// smem: zt[128][72]h, et[2][128][72]h (cp.async double buffer),
//       e2s[2][128]f (staged as e2+1 so s' > 0), rowmin[128]u (float bits).
// Epilogue: per code-pair fmaf x2 + fmin x2 + 1 cmp; rare direct appends.
// ---------------------------------------------------------------------------
__global__ void __launch_bounds__(256, 3) k_passA() {
    extern __shared__ __align__(16) char smA[];
    __nv_bfloat16* zt = (__nv_bfloat16*)smA;                  // 9216 halves
    float*    e2s    = (float*)(smA + 55296);                 // 2*128 floats
    unsigned* rowmin = (unsigned*)(smA + 56320);              // 128

    const int tid  = threadIdx.x;
    const int lane = tid & 31;
    const int w    = tid >> 5;
    const int wm   = w >> 1;        // 0..3
    const int wn   = w & 1;         // 0..1
    const int gid  = lane >> 2;     // fragment row group
    const int qid  = lane & 3;      // fragment col pair
    const int r0   = blockIdx.x * AM;

    // ---- stage z tile (plain, once) ----
    const uint2* zb2 = (const uint2*)g_zb;
    #pragma unroll
    for (int it = 0; it < 8; it++) {
        int i  = tid + it * 256;       // 2048
        int r  = i >> 4;
        int c4 = i & 15;
        *(uint2*)(zt + r * LDT + c4 * 4) = zb2[(size_t)(r0 + r) * 16 + c4];
    }
    if (tid < AM) rowmin[tid] = __float_as_uint(__ldg(&g_rmin[r0 + tid]));

    // ---- prefetch e chunk 0 ----
    {
        unsigned etb = smem_u32(zt + 9216);
        const char* src0 = (const char*)g_eb;
        #pragma unroll
        for (int it = 0; it < 8; it++) {
            int i  = tid + it * 256;
            int r  = i >> 4;
            int c4 = i & 15;
            CP_ASYNC8(etb + (unsigned)(r * LDT + c4 * 4) * 2,
                      src0 + ((size_t)r * 64 + c4 * 4) * 2);
        }
        asm volatile("cp.async.commit_group;");
        if (tid < ACH) e2s[tid] = __ldg(&g_e2[tid]) + 1.0f;
    }
    __syncthreads();   // zt + rowmin visible

    // ---- A fragments (held across all chunks) ----
    unsigned a[2][4][4];
    {
        unsigned ztb = smem_u32(zt);
        #pragma unroll
        for (int tm = 0; tm < 2; tm++)
            #pragma unroll
            for (int kt = 0; kt < 4; kt++) {
                int R0 = wm * 32 + tm * 16;
                unsigned addr = ztb +
                    (unsigned)((R0 + (lane & 15)) * LDT + kt * 16 +
                               ((lane >> 4) << 3)) * 2;
                asm volatile(
                    "ldmatrix.sync.aligned.m8n8.x4.shared.b16 {%0,%1,%2,%3}, [%4];"
                    : "=r"(a[tm][kt][0]), "=r"(a[tm][kt][1]),
                      "=r"(a[tm][kt][2]), "=r"(a[tm][kt][3])
                    : "r"(addr));
            }
    }

    // thread's 4 row slots: slot = tm*2 + jh -> rl = wm*32 + tm*16 + gid + jh*8
    int rls[4];
    #pragma unroll
    for (int slot = 0; slot < 4; slot++)
        rls[slot] = wm * 32 + (slot >> 1) * 16 + gid + (slot & 1) * 8;

    for (int ch = 0; ch < NACH; ch++) {
        asm volatile("cp.async.wait_group 0;");
        __syncthreads();   // current et/e2s visible; prev epilogue done

        if (ch + 1 < NACH) {
            int nb2 = (ch + 1) & 1;
            unsigned etb = smem_u32(zt + 9216 + nb2 * 9216);
            const char* src = (const char*)g_eb +
                              (size_t)(ch + 1) * ACH * 64 * 2;
            #pragma unroll
            for (int it = 0; it < 8; it++) {
                int i  = tid + it * 256;
                int r  = i >> 4;
                int c4 = i & 15;
                CP_ASYNC8(etb + (unsigned)(r * LDT + c4 * 4) * 2,
                          src + ((size_t)r * 64 + c4 * 4) * 2);
            }
            asm volatile("cp.async.commit_group;");
            if (tid < ACH)
                e2s[nb2 * ACH + tid] = __ldg(&g_e2[(ch + 1) * ACH + tid]) + 1.0f;
        }

        // per-chunk thresholds (stale-read safe: only over-collects)
        float thr[4], lmin[4];
        #pragma unroll
        for (int slot = 0; slot < 4; slot++) {
            thr[slot]  = __uint_as_float(rowmin[rls[slot]]) + MARGIN;
            lmin[slot] = FLT_MAX;
        }

        const int cb = ch & 1;
        unsigned et_base = smem_u32(zt + 9216 + cb * 9216);
        const float* e2c = e2s + cb * ACH;

        #pragma unroll
        for (int nt = 0; nt < 8; nt++) {
            const int nb = wn * 64 + nt * 8;

            unsigned b0[4], b1[4];
            #pragma unroll
            for (int kt = 0; kt < 4; kt++) {
                unsigned addr = et_base +
                    (unsigned)((nb + (lane & 7)) * LDT + kt * 16 +
                               (((lane >> 3) & 1) << 3)) * 2;
                asm volatile(
                    "ldmatrix.sync.aligned.m8n8.x2.shared.b16 {%0,%1}, [%2];"
                    : "=r"(b0[kt]), "=r"(b1[kt]) : "r"(addr));
            }

            float c0[4] = {0.f, 0.f, 0.f, 0.f};
            float c1[4] = {0.f, 0.f, 0.f, 0.f};
            #pragma unroll
            for (int kt = 0; kt < 4; kt++) {
                MMA16816(c0, a[0][kt], b0[kt], b1[kt]);
                MMA16816(c1, a[1][kt], b0[kt], b1[kt]);
            }

            const float e2p0 = e2c[nb + qid * 2];
            const float e2p1 = e2c[nb + qid * 2 + 1];

            #pragma unroll
            for (int tm = 0; tm < 2; tm++) {
                const float* cc = tm ? c1 : c0;
                #pragma unroll
                for (int jh = 0; jh < 2; jh++) {
                    int slot = tm * 2 + jh;
                    float s0 = fmaf(-2.f, cc[jh * 2],     e2p0);
                    float s1 = fmaf(-2.f, cc[jh * 2 + 1], e2p1);
                    float m2 = fminf(s0, s1);
                    lmin[slot] = fminf(lmin[slot], m2);
                    if (m2 <= thr[slot]) {                  // rare
                        unsigned codeb = (unsigned)(ch * ACH + nb + qid * 2);
                        unsigned rw = (unsigned)(r0 + rls[slot]) << 12;
                        if (s0 <= thr[slot]) {
                            unsigned pos = atomicAdd(&g_ncand, 1u);
                            if (pos < CAND_CAP) g_cand[pos] = rw | codeb;
                        }
                        if (s1 <= thr[slot]) {
                            unsigned pos = atomicAdd(&g_ncand, 1u);
                            if (pos < CAND_CAP) g_cand[pos] = rw | (codeb + 1);
                        }
                    }
                }
            }
        }

        // fold chunk minima into shared rowmin (visible next chunk via sync)
        #pragma unroll
        for (int slot = 0; slot < 4; slot++)
            atomicMin(&rowmin[rls[slot]], __float_as_uint(lmin[slot]));
    }
}

// ---------------------------------------------------------------------------
// K2 (pass B): exact reference-rounded rescreen, 8 LANES PER CANDIDATE
// (4 candidates/warp). Lane sl in [0,8): loads z/e float4 pairs (256B
// coalesced per candidate), 8-FMA chain, 3-level sub-warp shuffle.
// Final rounding unchanged: v = fsub_rn(fadd_rn(zz,ee), 2*dot); winner
// via atomicMin on (v_bits<<32)|code (exact order + lowest-index ties).
// Association change is safe: dot err ~1e-9 << ulp(64)~7.6e-6 grid
// (empirically re-verified R8->R9: identical rel_err).
// ---------------------------------------------------------------------------
__global__ void k_rescreen(const float* __restrict__ z,
                           const float* __restrict__ emb) {
    unsigned n = g_ncand;
    if (n > CAND_CAP) n = CAND_CAP;
    const int ln  = threadIdx.x & 31;
    const int sub = ln >> 3;            // candidate slot within warp
    const int sl  = ln & 7;             // lane within candidate group
    const unsigned gmask = 0xFFu << (sub * 8);
    const unsigned gw = (blockIdx.x * blockDim.x + threadIdx.x) >> 5;
    const unsigned nw = (gridDim.x * blockDim.x) >> 5;

    for (unsigned base = gw * 4; base < n; base += nw * 4) {
        unsigned i = base + (unsigned)sub;
        if (i < n) {                    // uniform within each 8-lane group
            unsigned cd = __ldg(&g_cand[i]);
            unsigned row  = cd >> 12;
            unsigned code = cd & 4095u;
            const float4* zr = (const float4*)(z   + (size_t)row  * DIM) + sl * 2;
            const float4* er = (const float4*)(emb + (size_t)code * DIM) + sl * 2;
            float4 z0 = __ldg(zr), z1 = __ldg(zr + 1);
            float4 e0 = __ldg(er), e1 = __ldg(er + 1);
            float p = __fmul_rn(z0.x, e0.x);
            p = __fmaf_rn(z0.y, e0.y, p);
            p = __fmaf_rn(z0.z, e0.z, p);
            p = __fmaf_rn(z0.w, e0.w, p);
            p = __fmaf_rn(z1.x, e1.x, p);
            p = __fmaf_rn(z1.y, e1.y, p);
            p = __fmaf_rn(z1.z, e1.z, p);
            p = __fmaf_rn(z1.w, e1.w, p);
            p += __shfl_xor_sync(gmask, p, 1);
            p += __shfl_xor_sync(gmask, p, 2);
            p += __shfl_xor_sync(gmask, p, 4);
            if (sl == 0) {
                float v = __fsub_rn(
                    __fadd_rn(__ldg(&g_zz[row]), __ldg(&g_e2[code])),
                    __fmul_rn(2.f, p));
                unsigned long long key =
                    ((unsigned long long)__float_as_uint(v) << 32) | code;
                atomicMin(&g_best[row], key);
            }
        }
    }
}

// ---------------------------------------------------------------------------
// K3: gather z_q, straight-through output, loss partial, scatter counts/dw.
// ---------------------------------------------------------------------------
__global__ void k_scatter(const float* __restrict__ z, const float* __restrict__ emb,
                          float* __restrict__ out)
{
    int row = blockIdx.x * 8 + (threadIdx.x >> 5);
    int ln  = threadIdx.x & 31;
    int idx = (int)(unsigned)(g_best[row] & 0xffffffffull);
    const float* zr = z   + (size_t)row * DIM;
    const float* er = emb + (size_t)idx * DIM;
    float* zq = out + O_ZQ + (size_t)row * DIM;
    float l = 0.f;
    #pragma unroll
    for (int t = 0; t < 2; t++) {
        int j = ln + 32 * t;
        float zv = zr[j], ev = __ldg(er + j);
        zq[j] = __fadd_rn(zv, __fsub_rn(ev, zv));
        float dd = __fsub_rn(zv, ev);
        l += dd * dd;
        atomicAdd(&g_dw[idx * DIM + j], zv);
    }
    if (ln == 0) {
        atomicAdd(&g_counts[idx], 1.f);
        out[O_IND + row] = (float)idx;
    }
    #pragma unroll
    for (int o = 16; o; o >>= 1) l += __shfl_xor_sync(0xffffffffu, l, o);
    __shared__ float sl2[8];
    if (ln == 0) sl2[threadIdx.x >> 5] = l;
    __syncthreads();
    if (threadIdx.x == 0) {
        float s = 0.f;
        #pragma unroll
        for (int w2 = 0; w2 < 8; w2++) s += sl2[w2];
        atomicAdd(&g_losssum, s);
    }
}

// ---------------------------------------------------------------------------
// K4: new_cluster_size, n, normalized cluster size, loss (single block)
// ---------------------------------------------------------------------------
__global__ void k_fin1(const float* __restrict__ ema_cs, float* __restrict__ out)
{
    int tid = threadIdx.x;  // 1024
    float ncs[4];
    float s = 0.f;
    #pragma unroll
    for (int j = 0; j < 4; j++) {
        int k = tid + j * 1024;
        float v = 0.99f * ema_cs[k] + 0.01f * g_counts[k];
        ncs[j] = v; s += v;
        out[O_NCS + k] = v;
    }
    __shared__ float sp[32];
    #pragma unroll
    for (int o = 16; o; o >>= 1) s += __shfl_xor_sync(0xffffffffu, s, o);
    if ((tid & 31) == 0) sp[tid >> 5] = s;
    __syncthreads();
    if (tid < 32) {
        float v = sp[tid];
        #pragma unroll
        for (int o = 16; o; o >>= 1) v += __shfl_xor_sync(0xffffffffu, v, o);
        if (tid == 0) sp[0] = v;
    }
    __syncthreads();
    float n = sp[0];
    float denom = n + (float)KN * 1e-5f;
    #pragma unroll
    for (int j = 0; j < 4; j++) {
        int k = tid + j * 1024;
        g_cs[k] = (ncs[j] + 1e-5f) / denom * n;
    }
    if (tid == 0) out[O_LOSS] = 0.25f * (g_losssum / 2097152.0f);
}

// ---------------------------------------------------------------------------
// K5: new_ema_w and new_embedding
// ---------------------------------------------------------------------------
__global__ void k_fin2(const float* __restrict__ ema_w, float* __restrict__ out)
{
    int i = blockIdx.x * blockDim.x + threadIdx.x;   // 262144 total
    float nw = 0.99f * ema_w[i] + 0.01f * g_dw[i];
    out[O_NW + i] = nw;
    out[O_NE + i] = __fdiv_rn(nw, g_cs[i >> 6]);
}

// ---------------------------------------------------------------------------
#define SMA_BYTES 56832

extern "C" void kernel_launch(void* const* d_in, const int* in_sizes, int n_in,
                              void* d_out, int out_size)
{
    const float* z      = (const float*)d_in[0];
    const float* emb    = (const float*)d_in[1];
    const float* ema_cs = (const float*)d_in[2];
    const float* ema_w  = (const float*)d_in[3];
    float* out = (float*)d_out;

    cudaFuncSetAttribute(k_passA, cudaFuncAttributeMaxDynamicSharedMemorySize,
                         SMA_BYTES);

    k_prep    <<<256, 256>>>(z, emb);
    k_warm    <<<NROWS / 256, 256>>>(z, emb);
    k_passA   <<<ABLK, 256, SMA_BYTES>>>();
    k_rescreen<<<1024, 256>>>(z, emb);
    k_scatter <<<NROWS / 8, 256>>>(z, emb, out);
    k_fin1    <<<1, 1024>>>(ema_cs, out);
    k_fin2    <<<KN * DIM / 256, 256>>>(ema_w, out);
}

// round 13
// speedup vs baseline: 1.7427x; 1.0779x over previous
#include <cuda_runtime.h>
#include <cuda_bf16.h>
#include <cfloat>

// ---------------------------------------------------------------------------
// VectorQuantizer (VQ-VAE) fused pipeline, sm_100 (no 'a' features for ptxas
// -> legacy mma.sync bf16, likely fp-pipe emulated; passA ~250us).
// (Round-13 resubmit #2: R11 and R12 both hit broker-level container
//  failures BEFORE compile -- source cannot affect container acquisition,
//  and R2/R5 showed identical-source resubmits pass cleanly. Identical
//  kernel so the R11 prediction finally gets measured.)
// R10 -> R11..R13:
//   - k_prep split into k_prep_a/k_prep_b (vectorized float4/bf16x2) -- also
//     moves k_passA to launch index 3, which is what the ncu capture shows.
//   - k_rescreen: 2 candidates in flight per 8-lane group (ILP for latency).
// passA itself untouched (R10-proven).
// ---------------------------------------------------------------------------

#define NROWS 32768
#define KN    4096
#define DIM   64

// pass A tiling
#define AM    128            // rows per CTA
#define ABLK  (NROWS / AM)   // 256 CTAs
#define ACH   128            // codes per chunk
#define NACH  (KN / ACH)     // 32
#define LDT   72             // smem tile row stride (halves): conflict-free ldmatrix
#define MARGIN 6e-4f
#define CAND_CAP (1u << 22)  // 4M candidate slots

// output offsets (elements)
#define O_ZQ   0
#define O_IND  2097152
#define O_LOSS 2129920
#define O_NE   2129921
#define O_NCS  2392065
#define O_NW   2396161

// scratch
__device__ float              g_zz[NROWS];
__device__ float              g_e2[KN];
__device__ float              g_rmin[NROWS];     // warm-start row min (exact, +slack)
__device__ float              g_counts[KN];
__device__ float              g_dw[KN * DIM];
__device__ float              g_cs[KN];
__device__ float              g_losssum;
__device__ unsigned long long g_best[NROWS];     // (v_bits<<32)|code
__device__ unsigned           g_cand[CAND_CAP];  // (row<<12)|code
__device__ unsigned           g_ncand;
__device__ __nv_bfloat16      g_zb[NROWS * DIM];
__device__ __nv_bfloat16      g_eb[KN * DIM];

__device__ __forceinline__ unsigned smem_u32(const void* p) {
    unsigned r;
    asm("{ .reg .u64 t; cvta.to.shared.u64 t, %1; cvt.u32.u64 %0, t; }"
        : "=r"(r) : "l"(p));
    return r;
}

#define MMA16816(c, A, B0, B1) \
    asm volatile("mma.sync.aligned.m16n8k16.row.col.f32.bf16.bf16.f32 " \
        "{%0,%1,%2,%3}, {%4,%5,%6,%7}, {%8,%9}, {%0,%1,%2,%3};" \
        : "+f"((c)[0]), "+f"((c)[1]), "+f"((c)[2]), "+f"((c)[3]) \
        : "r"((A)[0]), "r"((A)[1]), "r"((A)[2]), "r"((A)[3]), \
          "r"(B0), "r"(B1))

#define CP_ASYNC8(dst, src) \
    asm volatile("cp.async.ca.shared.global [%0], [%1], 8;" \
        :: "r"(dst), "l"(src))

// ---------------------------------------------------------------------------
// K0a: zero g_dw, convert emb->bf16 (vectorized), ||e||^2 (exact reference
// rounding: sequential fadd_rn(fmul_rn), order preserved), counts, globals.
// ---------------------------------------------------------------------------
__global__ void k_prep_a(const float* __restrict__ emb) {
    int i = blockIdx.x * blockDim.x + threadIdx.x;   // 16384 threads
    #pragma unroll
    for (int it = 0; it < 4; it++) {
        int j = i + it * 16384;                      // 65536 uint4/uint2 slots
        ((uint4*)g_dw)[j] = make_uint4(0u, 0u, 0u, 0u);
        float4 v = __ldg((const float4*)emb + j);
        __nv_bfloat162 lo = __float22bfloat162_rn(make_float2(v.x, v.y));
        __nv_bfloat162 hi = __float22bfloat162_rn(make_float2(v.z, v.w));
        uint2 u;
        u.x = *(unsigned*)&lo;
        u.y = *(unsigned*)&hi;
        ((uint2*)g_eb)[j] = u;
    }
    if (i < KN) {
        g_counts[i] = 0.f;
        const float4* e4 = (const float4*)(emb + (size_t)i * DIM);
        float s = 0.f;
        #pragma unroll
        for (int q = 0; q < 16; q++) {
            float4 v = __ldg(e4 + q);
            s = __fadd_rn(s, __fmul_rn(v.x, v.x));
            s = __fadd_rn(s, __fmul_rn(v.y, v.y));
            s = __fadd_rn(s, __fmul_rn(v.z, v.z));
            s = __fadd_rn(s, __fmul_rn(v.w, v.w));
        }
        g_e2[i] = s;
    }
    if (i == 0) { g_losssum = 0.f; g_ncand = 0u; }
}

// ---------------------------------------------------------------------------
// K0b: convert z->bf16 (vectorized), ||z||^2 (sequential rounding), g_best.
// ---------------------------------------------------------------------------
__global__ void k_prep_b(const float* __restrict__ z) {
    int i = blockIdx.x * blockDim.x + threadIdx.x;   // 65536 threads
    #pragma unroll
    for (int it = 0; it < 8; it++) {
        int j = i + it * 65536;                      // 524288 float4 slots
        float4 v = __ldg((const float4*)z + j);
        __nv_bfloat162 lo = __float22bfloat162_rn(make_float2(v.x, v.y));
        __nv_bfloat162 hi = __float22bfloat162_rn(make_float2(v.z, v.w));
        uint2 u;
        u.x = *(unsigned*)&lo;
        u.y = *(unsigned*)&hi;
        ((uint2*)g_zb)[j] = u;
    }
    if (i < NROWS) {
        g_best[i] = 0xFFFFFFFFFFFFFFFFull;
        const float4* z4 = (const float4*)(z + (size_t)i * DIM);
        float s = 0.f;
        #pragma unroll
        for (int q = 0; q < 16; q++) {
            float4 v = __ldg(z4 + q);
            s = __fadd_rn(s, __fmul_rn(v.x, v.x));
            s = __fadd_rn(s, __fmul_rn(v.y, v.y));
            s = __fadd_rn(s, __fmul_rn(v.z, v.z));
            s = __fadd_rn(s, __fmul_rn(v.w, v.w));
        }
        g_zz[i] = s;
    }
}

// ---------------------------------------------------------------------------
// K0c: warm-start rowmin. Every row: exact fp32 s'=1+||e||^2-2 z.e over the
// SAME 32 sampled codes (smem-broadcast). +1e-4 slack covers exact-vs-bf16
// crossover at the threshold.
// ---------------------------------------------------------------------------
__global__ void k_warm(const float* __restrict__ z, const float* __restrict__ emb) {
    __shared__ float ec[32 * DIM];   // 8 KB sampled codes
    __shared__ float ee2[32];
    const int tid = threadIdx.x;     // 256
    for (int i = tid; i < 32 * DIM; i += 256) {
        int j = i >> 6, d = i & 63;
        ec[i] = __ldg(&emb[(size_t)(j * 128 + 64) * DIM + d]);
    }
    __syncthreads();
    if (tid < 32) {
        float s = 0.f;
        #pragma unroll
        for (int d = 0; d < DIM; d++) { float v = ec[tid * DIM + d]; s += v * v; }
        ee2[tid] = 1.0f + s;
    }
    __syncthreads();

    int row = blockIdx.x * 256 + tid;
    const float4* zr4 = (const float4*)(z + (size_t)row * DIM);
    float4 zl[16];
    #pragma unroll
    for (int q = 0; q < 16; q++) zl[q] = zr4[q];

    float best = FLT_MAX;
    #pragma unroll 4
    for (int j = 0; j < 32; j++) {
        const float4* e4 = (const float4*)(ec + j * DIM);
        float dot = 0.f;
        #pragma unroll
        for (int q = 0; q < 16; q++) {
            float4 e = e4[q];
            dot = fmaf(zl[q].x, e.x, dot);
            dot = fmaf(zl[q].y, e.y, dot);
            dot = fmaf(zl[q].z, e.z, dot);
            dot = fmaf(zl[q].w, e.w, dot);
        }
        best = fminf(best, fmaf(-2.f, dot, ee2[j]));
    }
    g_rmin[row] = best + 1e-4f;
}

// ---------------------------------------------------------------------------
// K1 (pass A): bf16 mma.sync distance scan + margin collection (unchanged,
// R10-proven). Launch index 3 -> gets profiled by the ncu capture.
// ---------------------------------------------------------------------------
__global__ void __launch_bounds__(256, 3) k_passA() {
    extern __shared__ __align__(16) char smA[];
    __nv_bfloat16* zt = (__nv_bfloat16*)smA;                  // 9216 halves
    float*    e2s    = (float*)(smA + 55296);                 // 2*128 floats
    unsigned* rowmin = (unsigned*)(smA + 56320);              // 128

    const int tid  = threadIdx.x;
    const int lane = tid & 31;
    const int w    = tid >> 5;
    const int wm   = w >> 1;        // 0..3
    const int wn   = w & 1;         // 0..1
    const int gid  = lane >> 2;     // fragment row group
    const int qid  = lane & 3;      // fragment col pair
    const int r0   = blockIdx.x * AM;

    // ---- stage z tile (plain, once) ----
    const uint2* zb2 = (const uint2*)g_zb;
    #pragma unroll
    for (int it = 0; it < 8; it++) {
        int i  = tid + it * 256;       // 2048
        int r  = i >> 4;
        int c4 = i & 15;
        *(uint2*)(zt + r * LDT + c4 * 4) = zb2[(size_t)(r0 + r) * 16 + c4];
    }
    if (tid < AM) rowmin[tid] = __float_as_uint(__ldg(&g_rmin[r0 + tid]));

    // ---- prefetch e chunk 0 ----
    {
        unsigned etb = smem_u32(zt + 9216);
        const char* src0 = (const char*)g_eb;
        #pragma unroll
        for (int it = 0; it < 8; it++) {
            int i  = tid + it * 256;
            int r  = i >> 4;
            int c4 = i & 15;
            CP_ASYNC8(etb + (unsigned)(r * LDT + c4 * 4) * 2,
                      src0 + ((size_t)r * 64 + c4 * 4) * 2);
        }
        asm volatile("cp.async.commit_group;");
        if (tid < ACH) e2s[tid] = __ldg(&g_e2[tid]) + 1.0f;
    }
    __syncthreads();   // zt + rowmin visible

    // ---- A fragments (held across all chunks) ----
    unsigned a[2][4][4];
    {
        unsigned ztb = smem_u32(zt);
        #pragma unroll
        for (int tm = 0; tm < 2; tm++)
            #pragma unroll
            for (int kt = 0; kt < 4; kt++) {
                int R0 = wm * 32 + tm * 16;
                unsigned addr = ztb +
                    (unsigned)((R0 + (lane & 15)) * LDT + kt * 16 +
                               ((lane >> 4) << 3)) * 2;
                asm volatile(
                    "ldmatrix.sync.aligned.m8n8.x4.shared.b16 {%0,%1,%2,%3}, [%4];"
                    : "=r"(a[tm][kt][0]), "=r"(a[tm][kt][1]),
                      "=r"(a[tm][kt][2]), "=r"(a[tm][kt][3])
                    : "r"(addr));
            }
    }

    // thread's 4 row slots: slot = tm*2 + jh -> rl = wm*32 + tm*16 + gid + jh*8
    int rls[4];
    #pragma unroll
    for (int slot = 0; slot < 4; slot++)
        rls[slot] = wm * 32 + (slot >> 1) * 16 + gid + (slot & 1) * 8;

    for (int ch = 0; ch < NACH; ch++) {
        asm volatile("cp.async.wait_group 0;");
        __syncthreads();   // current et/e2s visible; prev epilogue done

        if (ch + 1 < NACH) {
            int nb2 = (ch + 1) & 1;
            unsigned etb = smem_u32(zt + 9216 + nb2 * 9216);
            const char* src = (const char*)g_eb +
                              (size_t)(ch + 1) * ACH * 64 * 2;
            #pragma unroll
            for (int it = 0; it < 8; it++) {
                int i  = tid + it * 256;
                int r  = i >> 4;
                int c4 = i & 15;
                CP_ASYNC8(etb + (unsigned)(r * LDT + c4 * 4) * 2,
                          src + ((size_t)r * 64 + c4 * 4) * 2);
            }
            asm volatile("cp.async.commit_group;");
            if (tid < ACH)
                e2s[nb2 * ACH + tid] = __ldg(&g_e2[(ch + 1) * ACH + tid]) + 1.0f;
        }

        // per-chunk thresholds (stale-read safe: only over-collects)
        float thr[4], lmin[4];
        #pragma unroll
        for (int slot = 0; slot < 4; slot++) {
            thr[slot]  = __uint_as_float(rowmin[rls[slot]]) + MARGIN;
            lmin[slot] = FLT_MAX;
        }

        const int cb = ch & 1;
        unsigned et_base = smem_u32(zt + 9216 + cb * 9216);
        const float* e2c = e2s + cb * ACH;

        #pragma unroll
        for (int nt = 0; nt < 8; nt++) {
            const int nb = wn * 64 + nt * 8;

            unsigned b0[4], b1[4];
            #pragma unroll
            for (int kt = 0; kt < 4; kt++) {
                unsigned addr = et_base +
                    (unsigned)((nb + (lane & 7)) * LDT + kt * 16 +
                               (((lane >> 3) & 1) << 3)) * 2;
                asm volatile(
                    "ldmatrix.sync.aligned.m8n8.x2.shared.b16 {%0,%1}, [%2];"
                    : "=r"(b0[kt]), "=r"(b1[kt]) : "r"(addr));
            }

            float c0[4] = {0.f, 0.f, 0.f, 0.f};
            float c1[4] = {0.f, 0.f, 0.f, 0.f};
            #pragma unroll
            for (int kt = 0; kt < 4; kt++) {
                MMA16816(c0, a[0][kt], b0[kt], b1[kt]);
                MMA16816(c1, a[1][kt], b0[kt], b1[kt]);
            }

            const float e2p0 = e2c[nb + qid * 2];
            const float e2p1 = e2c[nb + qid * 2 + 1];

            #pragma unroll
            for (int tm = 0; tm < 2; tm++) {
                const float* cc = tm ? c1 : c0;
                #pragma unroll
                for (int jh = 0; jh < 2; jh++) {
                    int slot = tm * 2 + jh;
                    float s0 = fmaf(-2.f, cc[jh * 2],     e2p0);
                    float s1 = fmaf(-2.f, cc[jh * 2 + 1], e2p1);
                    float m2 = fminf(s0, s1);
                    lmin[slot] = fminf(lmin[slot], m2);
                    if (m2 <= thr[slot]) {                  // rare
                        unsigned codeb = (unsigned)(ch * ACH + nb + qid * 2);
                        unsigned rw = (unsigned)(r0 + rls[slot]) << 12;
                        if (s0 <= thr[slot]) {
                            unsigned pos = atomicAdd(&g_ncand, 1u);
                            if (pos < CAND_CAP) g_cand[pos] = rw | codeb;
                        }
                        if (s1 <= thr[slot]) {
                            unsigned pos = atomicAdd(&g_ncand, 1u);
                            if (pos < CAND_CAP) g_cand[pos] = rw | (codeb + 1);
                        }
                    }
                }
            }
        }

        // fold chunk minima into shared rowmin (visible next chunk via sync)
        #pragma unroll
        for (int slot = 0; slot < 4; slot++)
            atomicMin(&rowmin[rls[slot]], __float_as_uint(lmin[slot]));
    }
}

// ---------------------------------------------------------------------------
// K2 (pass B): exact reference-rounded rescreen, 8 lanes/candidate,
// TWO candidates in flight per group (loads batched up front for ILP).
// Final rounding unchanged: v = fsub_rn(fadd_rn(zz,ee), 2*dot); winner via
// atomicMin on (v_bits<<32)|code. Association safety: dot err ~1e-9 <<
// ulp(64)~7.6e-6 grid (empirically verified R8->R10: identical rel_err).
// ---------------------------------------------------------------------------
__global__ void k_rescreen(const float* __restrict__ z,
                           const float* __restrict__ emb) {
    unsigned n = g_ncand;
    if (n > CAND_CAP) n = CAND_CAP;
    const int ln  = threadIdx.x & 31;
    const int sub = ln >> 3;            // candidate slot within warp
    const int sl  = ln & 7;             // lane within candidate group
    const unsigned gmask = 0xFFu << (sub * 8);
    const unsigned gw = (blockIdx.x * blockDim.x + threadIdx.x) >> 5;
    const unsigned nw = (gridDim.x * blockDim.x) >> 5;

    for (unsigned base = gw * 8; base < n; base += nw * 8) {
        unsigned i0 = base + (unsigned)sub;
        unsigned i1 = base + 4u + (unsigned)sub;
        bool ok0 = i0 < n, ok1 = i1 < n;
        unsigned j0 = ok0 ? i0 : 0u, j1 = ok1 ? i1 : 0u;
        unsigned cd0 = __ldg(&g_cand[j0]);
        unsigned cd1 = __ldg(&g_cand[j1]);
        unsigned row0 = cd0 >> 12, code0 = cd0 & 4095u;
        unsigned row1 = cd1 >> 12, code1 = cd1 & 4095u;
        const float4* zr0 = (const float4*)(z   + (size_t)row0  * DIM) + sl * 2;
        const float4* er0 = (const float4*)(emb + (size_t)code0 * DIM) + sl * 2;
        const float4* zr1 = (const float4*)(z   + (size_t)row1  * DIM) + sl * 2;
        const float4* er1 = (const float4*)(emb + (size_t)code1 * DIM) + sl * 2;
        float4 a0 = __ldg(zr0), a1 = __ldg(zr0 + 1);
        float4 b0 = __ldg(er0), b1 = __ldg(er0 + 1);
        float4 a2 = __ldg(zr1), a3 = __ldg(zr1 + 1);
        float4 b2 = __ldg(er1), b3 = __ldg(er1 + 1);
        float p0 = __fmul_rn(a0.x, b0.x);
        float p1 = __fmul_rn(a2.x, b2.x);
        p0 = __fmaf_rn(a0.y, b0.y, p0); p1 = __fmaf_rn(a2.y, b2.y, p1);
        p0 = __fmaf_rn(a0.z, b0.z, p0); p1 = __fmaf_rn(a2.z, b2.z, p1);
        p0 = __fmaf_rn(a0.w, b0.w, p0); p1 = __fmaf_rn(a2.w, b2.w, p1);
        p0 = __fmaf_rn(a1.x, b1.x, p0); p1 = __fmaf_rn(a3.x, b3.x, p1);
        p0 = __fmaf_rn(a1.y, b1.y, p0); p1 = __fmaf_rn(a3.y, b3.y, p1);
        p0 = __fmaf_rn(a1.z, b1.z, p0); p1 = __fmaf_rn(a3.z, b3.z, p1);
        p0 = __fmaf_rn(a1.w, b1.w, p0); p1 = __fmaf_rn(a3.w, b3.w, p1);
        p0 += __shfl_xor_sync(gmask, p0, 1);
        p1 += __shfl_xor_sync(gmask, p1, 1);
        p0 += __shfl_xor_sync(gmask, p0, 2);
        p1 += __shfl_xor_sync(gmask, p1, 2);
        p0 += __shfl_xor_sync(gmask, p0, 4);
        p1 += __shfl_xor_sync(gmask, p1, 4);
        if (sl == 0) {
            if (ok0) {
                float v = __fsub_rn(
                    __fadd_rn(__ldg(&g_zz[row0]), __ldg(&g_e2[code0])),
                    __fmul_rn(2.f, p0));
                unsigned long long key =
                    ((unsigned long long)__float_as_uint(v) << 32) | code0;
                atomicMin(&g_best[row0], key);
            }
            if (ok1) {
                float v = __fsub_rn(
                    __fadd_rn(__ldg(&g_zz[row1]), __ldg(&g_e2[code1])),
                    __fmul_rn(2.f, p1));
                unsigned long long key =
                    ((unsigned long long)__float_as_uint(v) << 32) | code1;
                atomicMin(&g_best[row1], key);
            }
        }
    }
}

// ---------------------------------------------------------------------------
// K3: gather z_q, straight-through output, loss partial, scatter counts/dw.
// ---------------------------------------------------------------------------
__global__ void k_scatter(const float* __restrict__ z, const float* __restrict__ emb,
                          float* __restrict__ out)
{
    int row = blockIdx.x * 8 + (threadIdx.x >> 5);
    int ln  = threadIdx.x & 31;
    int idx = (int)(unsigned)(g_best[row] & 0xffffffffull);
    const float* zr = z   + (size_t)row * DIM;
    const float* er = emb + (size_t)idx * DIM;
    float* zq = out + O_ZQ + (size_t)row * DIM;
    float l = 0.f;
    #pragma unroll
    for (int t = 0; t < 2; t++) {
        int j = ln + 32 * t;
        float zv = zr[j], ev = __ldg(er + j);
        zq[j] = __fadd_rn(zv, __fsub_rn(ev, zv));
        float dd = __fsub_rn(zv, ev);
        l += dd * dd;
        atomicAdd(&g_dw[idx * DIM + j], zv);
    }
    if (ln == 0) {
        atomicAdd(&g_counts[idx], 1.f);
        out[O_IND + row] = (float)idx;
    }
    #pragma unroll
    for (int o = 16; o; o >>= 1) l += __shfl_xor_sync(0xffffffffu, l, o);
    __shared__ float sl2[8];
    if (ln == 0) sl2[threadIdx.x >> 5] = l;
    __syncthreads();
    if (threadIdx.x == 0) {
        float s = 0.f;
        #pragma unroll
        for (int w2 = 0; w2 < 8; w2++) s += sl2[w2];
        atomicAdd(&g_losssum, s);
    }
}

// ---------------------------------------------------------------------------
// K4: new_cluster_size, n, normalized cluster size, loss (single block)
// ---------------------------------------------------------------------------
__global__ void k_fin1(const float* __restrict__ ema_cs, float* __restrict__ out)
{
    int tid = threadIdx.x;  // 1024
    float ncs[4];
    float s = 0.f;
    #pragma unroll
    for (int j = 0; j < 4; j++) {
        int k = tid + j * 1024;
        float v = 0.99f * ema_cs[k] + 0.01f * g_counts[k];
        ncs[j] = v; s += v;
        out[O_NCS + k] = v;
    }
    __shared__ float sp[32];
    #pragma unroll
    for (int o = 16; o; o >>= 1) s += __shfl_xor_sync(0xffffffffu, s, o);
    if ((tid & 31) == 0) sp[tid >> 5] = s;
    __syncthreads();
    if (tid < 32) {
        float v = sp[tid];
        #pragma unroll
        for (int o = 16; o; o >>= 1) v += __shfl_xor_sync(0xffffffffu, v, o);
        if (tid == 0) sp[0] = v;
    }
    __syncthreads();
    float n = sp[0];
    float denom = n + (float)KN * 1e-5f;
    #pragma unroll
    for (int j = 0; j < 4; j++) {
        int k = tid + j * 1024;
        g_cs[k] = (ncs[j] + 1e-5f) / denom * n;
    }
    if (tid == 0) out[O_LOSS] = 0.25f * (g_losssum / 2097152.0f);
}

// ---------------------------------------------------------------------------
// K5: new_ema_w and new_embedding
// ---------------------------------------------------------------------------
__global__ void k_fin2(const float* __restrict__ ema_w, float* __restrict__ out)
{
    int i = blockIdx.x * blockDim.x + threadIdx.x;   // 262144 total
    float nw = 0.99f * ema_w[i] + 0.01f * g_dw[i];
    out[O_NW + i] = nw;
    out[O_NE + i] = __fdiv_rn(nw, g_cs[i >> 6]);
}

// ---------------------------------------------------------------------------
#define SMA_BYTES 56832

extern "C" void kernel_launch(void* const* d_in, const int* in_sizes, int n_in,
                              void* d_out, int out_size)
{
    const float* z      = (const float*)d_in[0];
    const float* emb    = (const float*)d_in[1];
    const float* ema_cs = (const float*)d_in[2];
    const float* ema_w  = (const float*)d_in[3];
    float* out = (float*)d_out;

    cudaFuncSetAttribute(k_passA, cudaFuncAttributeMaxDynamicSharedMemorySize,
                         SMA_BYTES);

    k_prep_a  <<<64, 256>>>(emb);                 // launch 0
    k_prep_b  <<<256, 256>>>(z);                  // launch 1
    k_warm    <<<NROWS / 256, 256>>>(z, emb);     // launch 2
    k_passA   <<<ABLK, 256, SMA_BYTES>>>();       // launch 3  <- profiled
    k_rescreen<<<1024, 256>>>(z, emb);            // launch 4
    k_scatter <<<NROWS / 8, 256>>>(z, emb, out);  // launch 5
    k_fin1    <<<1, 1024>>>(ema_cs, out);         // launch 6
    k_fin2    <<<KN * DIM / 256, 256>>>(ema_w, out); // launch 7
}